// round 2
// baseline (speedup 1.0000x reference)
#include <cuda_runtime.h>
#include <cuda_bf16.h>
#include <math.h>

// ---------------- problem constants ----------------
#define N_TOK   4096          // B*S
#define DMODEL  1024
#define NEXP    8
#define HID     1024
#define TOPK    2

#define TM      64            // GEMM tile M
#define TN      64            // GEMM tile N
#define TKK     16            // GEMM tile K
// max tiles: experts <= 4096*2/64 + 8 = 136, shared = 64 -> 200. pad to 208.
#define MAX_TILES 208
#define MAX_ROWS  (MAX_TILES * TM)   // 13312

// ---------------- device scratch (no allocs allowed) ----------------
__device__ int   g_counts[NEXP];
__device__ int   g_fill[NEXP];
__device__ float g_probs[N_TOK * NEXP];
__device__ float g_lse2[N_TOK];
__device__ float g_probs_sum[NEXP];
__device__ float g_zsum;
__device__ int   g_expert_idx[N_TOK * TOPK];
__device__ float g_gate_w[N_TOK * TOPK];
__device__ int   g_row_tok[MAX_ROWS];
__device__ float g_row_w[MAX_ROWS];
__device__ int   g_row_pos[N_TOK * TOPK];
__device__ int   g_seg_start[NEXP + 1];
__device__ int   g_tile_expert[MAX_TILES];
__device__ int   g_n_tiles;
__device__ float g_h[(size_t)MAX_ROWS * HID];    // SwiGLU hidden per dispatched row
__device__ float g_ro[(size_t)MAX_ROWS * DMODEL]; // per-row expert output

// ---------------- init ----------------
__global__ void init_kernel() {
    int i = blockIdx.x * blockDim.x + threadIdx.x;
    if (i < MAX_ROWS) g_row_tok[i] = -1;
    if (i < NEXP) { g_counts[i] = 0; g_fill[i] = 0; }
    if (i == 0) g_zsum = 0.0f;
}

// ---------------- router: logits, softmax, top-2, per-token loss terms ----------------
__global__ __launch_bounds__(128) void router_kernel(const float* __restrict__ x,
                                                     const float* __restrict__ wr) {
    int tok = blockIdx.x;
    int tid = threadIdx.x;
    const float* xr = x + (size_t)tok * DMODEL;

    float acc[NEXP];
#pragma unroll
    for (int e = 0; e < NEXP; e++) acc[e] = 0.0f;

    for (int d = tid; d < DMODEL; d += 128) {
        float xv = xr[d];
        const float4* w4 = (const float4*)(wr + (size_t)d * NEXP);
        float4 w0 = w4[0];
        float4 w1 = w4[1];
        acc[0] += xv * w0.x; acc[1] += xv * w0.y;
        acc[2] += xv * w0.z; acc[3] += xv * w0.w;
        acc[4] += xv * w1.x; acc[5] += xv * w1.y;
        acc[6] += xv * w1.z; acc[7] += xv * w1.w;
    }
    // warp reduce
#pragma unroll
    for (int off = 16; off > 0; off >>= 1)
#pragma unroll
        for (int e = 0; e < NEXP; e++)
            acc[e] += __shfl_down_sync(0xffffffffu, acc[e], off);

    __shared__ float s[4][NEXP];
    int w = tid >> 5, l = tid & 31;
    if (l == 0)
#pragma unroll
        for (int e = 0; e < NEXP; e++) s[w][e] = acc[e];
    __syncthreads();

    if (tid == 0) {
        float lg[NEXP];
#pragma unroll
        for (int e = 0; e < NEXP; e++)
            lg[e] = s[0][e] + s[1][e] + s[2][e] + s[3][e];
        float mx = lg[0];
#pragma unroll
        for (int e = 1; e < NEXP; e++) mx = fmaxf(mx, lg[e]);
        float p[NEXP], se = 0.0f;
#pragma unroll
        for (int e = 0; e < NEXP; e++) { p[e] = expf(lg[e] - mx); se += p[e]; }
        float inv = 1.0f / se;
#pragma unroll
        for (int e = 0; e < NEXP; e++) p[e] *= inv;
        float lse = mx + logf(se);

        // top-2 on logits (softmax is monotone; ties -> lowest index, matching lax.top_k)
        int b0 = 0;
#pragma unroll
        for (int e = 1; e < NEXP; e++) if (lg[e] > lg[b0]) b0 = e;
        int b1 = (b0 == 0) ? 1 : 0;
#pragma unroll
        for (int e = 0; e < NEXP; e++)
            if (e != b0 && lg[e] > lg[b1]) b1 = e;

        g_expert_idx[tok * 2 + 0] = b0;
        g_expert_idx[tok * 2 + 1] = b1;
        g_gate_w[tok * 2 + 0] = p[b0];
        g_gate_w[tok * 2 + 1] = p[b1];
        atomicAdd(&g_counts[b0], 1);
        atomicAdd(&g_counts[b1], 1);
#pragma unroll
        for (int e = 0; e < NEXP; e++) g_probs[(size_t)tok * NEXP + e] = p[e];
        g_lse2[tok] = lse * lse;
    }
}

// ---------------- deterministic reductions for aux losses ----------------
__global__ __launch_bounds__(256) void reduce_kernel() {
    int which = blockIdx.x;   // 0..7 = probs_sum[e], 8 = sum(lse^2)
    int tid = threadIdx.x;
    float s = 0.0f;
    if (which < NEXP) {
        for (int i = tid; i < N_TOK; i += 256) s += g_probs[(size_t)i * NEXP + which];
    } else {
        for (int i = tid; i < N_TOK; i += 256) s += g_lse2[i];
    }
#pragma unroll
    for (int off = 16; off > 0; off >>= 1)
        s += __shfl_down_sync(0xffffffffu, s, off);
    __shared__ float sm[8];
    if ((tid & 31) == 0) sm[tid >> 5] = s;
    __syncthreads();
    if (tid == 0) {
        float t = 0.0f;
#pragma unroll
        for (int i = 0; i < 8; i++) t += sm[i];
        if (which < NEXP) g_probs_sum[which] = t;
        else g_zsum = t;
    }
}

// ---------------- plan: tile-aligned per-expert segments (expert 8 = shared) ----------------
__global__ void plan_kernel() {
    if (threadIdx.x == 0 && blockIdx.x == 0) {
        int acc = 0;
        for (int e = 0; e <= NEXP; e++) {
            int c = (e < NEXP) ? g_counts[e] : N_TOK;
            g_seg_start[e] = acc;
            int ntile = (c + TM - 1) / TM;
            int t0 = acc / TM;
            for (int i = 0; i < ntile; i++) g_tile_expert[t0 + i] = e;
            acc += ntile * TM;
        }
        g_n_tiles = acc / TM;
    }
}

// ---------------- scatter tokens into dispatch rows ----------------
__global__ void scatter_kernel() {
    int tok = blockIdx.x * blockDim.x + threadIdx.x;
    if (tok >= N_TOK) return;
#pragma unroll
    for (int k = 0; k < TOPK; k++) {
        int e = g_expert_idx[tok * 2 + k];
        int p = g_seg_start[e] + atomicAdd(&g_fill[e], 1);
        g_row_tok[p] = tok;
        g_row_w[p] = g_gate_w[tok * 2 + k] * ((float)TOPK / (float)(TOPK + 1));
        g_row_pos[tok * 2 + k] = p;
    }
    int ps = g_seg_start[NEXP] + tok;
    g_row_tok[ps] = tok;
    g_row_w[ps] = 1.0f / (float)(TOPK + 1);
}

// ---------------- stage 1: h = silu(X@W1) * (X@W3), gathered rows ----------------
__global__ __launch_bounds__(256) void stage1_kernel(const float* __restrict__ x,
                                                     const float* __restrict__ w1,
                                                     const float* __restrict__ w3,
                                                     const float* __restrict__ sw1,
                                                     const float* __restrict__ sw3) {
    int t = blockIdx.x;
    if (t >= g_n_tiles) return;
    int e = g_tile_expert[t];
    const float* W1 = (e < NEXP) ? (w1 + (size_t)e * DMODEL * HID) : sw1;
    const float* W3 = (e < NEXP) ? (w3 + (size_t)e * DMODEL * HID) : sw3;
    int row0 = t * TM;
    int n0 = blockIdx.y * TN;

    __shared__ float As[TM][TKK + 1];
    __shared__ float B1s[TKK][TN];
    __shared__ float B3s[TKK][TN];
    __shared__ int toks[TM];

    int tid = threadIdx.x;
    if (tid < TM) toks[tid] = g_row_tok[row0 + tid];
    __syncthreads();

    int tx = tid & 15, ty = tid >> 4;
    float accg[4][4], accu[4][4];
#pragma unroll
    for (int i = 0; i < 4; i++)
#pragma unroll
        for (int j = 0; j < 4; j++) { accg[i][j] = 0.0f; accu[i][j] = 0.0f; }

    int am = tid >> 2;
    int akq = (tid & 3) * 4;
    int bk = tid >> 4;
    int bnq = (tid & 15) * 4;

    for (int kk = 0; kk < DMODEL; kk += TKK) {
        {
            int tok = toks[am];
            float4 v = make_float4(0.f, 0.f, 0.f, 0.f);
            if (tok >= 0) v = *(const float4*)&x[(size_t)tok * DMODEL + kk + akq];
            As[am][akq + 0] = v.x; As[am][akq + 1] = v.y;
            As[am][akq + 2] = v.z; As[am][akq + 3] = v.w;
        }
        {
            *(float4*)&B1s[bk][bnq] = *(const float4*)&W1[(size_t)(kk + bk) * HID + n0 + bnq];
            *(float4*)&B3s[bk][bnq] = *(const float4*)&W3[(size_t)(kk + bk) * HID + n0 + bnq];
        }
        __syncthreads();
#pragma unroll
        for (int k = 0; k < TKK; k++) {
            float a[4];
#pragma unroll
            for (int i = 0; i < 4; i++) a[i] = As[ty * 4 + i][k];
            float4 b1 = *(const float4*)&B1s[k][tx * 4];
            float4 b3 = *(const float4*)&B3s[k][tx * 4];
            float bg[4] = { b1.x, b1.y, b1.z, b1.w };
            float bu[4] = { b3.x, b3.y, b3.z, b3.w };
#pragma unroll
            for (int i = 0; i < 4; i++)
#pragma unroll
                for (int j = 0; j < 4; j++) {
                    accg[i][j] += a[i] * bg[j];
                    accu[i][j] += a[i] * bu[j];
                }
        }
        __syncthreads();
    }

#pragma unroll
    for (int i = 0; i < 4; i++) {
        int r = row0 + ty * 4 + i;
        float4 o;
        float gv, hv;
        gv = accg[i][0]; hv = gv / (1.0f + expf(-gv)) * accu[i][0]; o.x = hv;
        gv = accg[i][1]; hv = gv / (1.0f + expf(-gv)) * accu[i][1]; o.y = hv;
        gv = accg[i][2]; hv = gv / (1.0f + expf(-gv)) * accu[i][2]; o.z = hv;
        gv = accg[i][3]; hv = gv / (1.0f + expf(-gv)) * accu[i][3]; o.w = hv;
        *(float4*)&g_h[(size_t)r * HID + n0 + tx * 4] = o;
    }
}

// ---------------- stage 2: ro = h @ W2 ----------------
__global__ __launch_bounds__(256) void stage2_kernel(const float* __restrict__ w2,
                                                     const float* __restrict__ sw2) {
    int t = blockIdx.x;
    if (t >= g_n_tiles) return;
    int e = g_tile_expert[t];
    const float* W2 = (e < NEXP) ? (w2 + (size_t)e * HID * DMODEL) : sw2;
    int row0 = t * TM;
    int n0 = blockIdx.y * TN;

    __shared__ float As[TM][TKK + 1];
    __shared__ float Bs[TKK][TN];

    int tid = threadIdx.x;
    int tx = tid & 15, ty = tid >> 4;
    float acc[4][4];
#pragma unroll
    for (int i = 0; i < 4; i++)
#pragma unroll
        for (int j = 0; j < 4; j++) acc[i][j] = 0.0f;

    int am = tid >> 2;
    int akq = (tid & 3) * 4;
    int bk = tid >> 4;
    int bnq = (tid & 15) * 4;

    for (int kk = 0; kk < HID; kk += TKK) {
        {
            float4 v = *(const float4*)&g_h[(size_t)(row0 + am) * HID + kk + akq];
            As[am][akq + 0] = v.x; As[am][akq + 1] = v.y;
            As[am][akq + 2] = v.z; As[am][akq + 3] = v.w;
        }
        *(float4*)&Bs[bk][bnq] = *(const float4*)&W2[(size_t)(kk + bk) * DMODEL + n0 + bnq];
        __syncthreads();
#pragma unroll
        for (int k = 0; k < TKK; k++) {
            float a[4];
#pragma unroll
            for (int i = 0; i < 4; i++) a[i] = As[ty * 4 + i][k];
            float4 b = *(const float4*)&Bs[k][tx * 4];
            float bb[4] = { b.x, b.y, b.z, b.w };
#pragma unroll
            for (int i = 0; i < 4; i++)
#pragma unroll
                for (int j = 0; j < 4; j++)
                    acc[i][j] += a[i] * bb[j];
        }
        __syncthreads();
    }

#pragma unroll
    for (int i = 0; i < 4; i++) {
        int r = row0 + ty * 4 + i;
        float4 o = make_float4(acc[i][0], acc[i][1], acc[i][2], acc[i][3]);
        *(float4*)&g_ro[(size_t)r * DMODEL + n0 + tx * 4] = o;
    }
}

// ---------------- deterministic weighted combine ----------------
__global__ __launch_bounds__(256) void combine_kernel(float* __restrict__ out) {
    int tok = blockIdx.x;
    int p0 = g_row_pos[tok * 2 + 0];
    int p1 = g_row_pos[tok * 2 + 1];
    int ps = g_seg_start[NEXP] + tok;
    float w0 = g_row_w[p0];
    float w1 = g_row_w[p1];
    const float ws = 1.0f / (float)(TOPK + 1);
    for (int d = threadIdx.x; d < DMODEL; d += 256) {
        float v = w0 * g_ro[(size_t)p0 * DMODEL + d]
                + w1 * g_ro[(size_t)p1 * DMODEL + d]
                + ws * g_ro[(size_t)ps * DMODEL + d];
        out[(size_t)tok * DMODEL + d] = v;
    }
}

// ---------------- losses ----------------
__global__ void finalize_kernel(float* __restrict__ out) {
    if (threadIdx.x == 0 && blockIdx.x == 0) {
        float lb = 0.0f;
        for (int e = 0; e < NEXP; e++)
            lb += (float)g_counts[e] * g_probs_sum[e];
        // scale = E * LB_W / (NUM_LAYERS * n_tok * K)
        lb *= (float)NEXP * 0.01f / (16.0f * (float)N_TOK * (float)TOPK);
        out[(size_t)N_TOK * DMODEL + 0] = lb;
        out[(size_t)N_TOK * DMODEL + 1] = 0.001f * g_zsum / (float)N_TOK;
    }
}

// ---------------- launch ----------------
extern "C" void kernel_launch(void* const* d_in, const int* in_sizes, int n_in,
                              void* d_out, int out_size) {
    const float* x   = (const float*)d_in[0];
    const float* wr  = (const float*)d_in[1];
    const float* w1  = (const float*)d_in[2];
    const float* w3  = (const float*)d_in[3];
    const float* w2  = (const float*)d_in[4];
    const float* sw1 = (const float*)d_in[5];
    const float* sw3 = (const float*)d_in[6];
    const float* sw2 = (const float*)d_in[7];
    float* out = (float*)d_out;

    init_kernel<<<(MAX_ROWS + 255) / 256, 256>>>();
    router_kernel<<<N_TOK, 128>>>(x, wr);
    reduce_kernel<<<NEXP + 1, 256>>>();
    plan_kernel<<<1, 32>>>();
    scatter_kernel<<<(N_TOK + 255) / 256, 256>>>();
    stage1_kernel<<<dim3(MAX_TILES, HID / TN), 256>>>(x, w1, w3, sw1, sw3);
    stage2_kernel<<<dim3(MAX_TILES, DMODEL / TN), 256>>>(w2, sw2);
    combine_kernel<<<N_TOK, 256>>>(out);
    finalize_kernel<<<1, 32>>>(out);
}

// round 3
// speedup vs baseline: 1.8819x; 1.8819x over previous
#include <cuda_runtime.h>
#include <cuda_bf16.h>
#include <math.h>
#include <stdint.h>

// ---------------- problem constants ----------------
#define N_TOK   4096
#define DMODEL  1024
#define NEXP    8
#define HID     1024
#define TOPK    2

// GEMM tiling (mma.sync bf16 path)
#define BM 128
#define BN 64
#define BK 32
#define APAD 8              // A row stride = 40 elems (80B) -> conflict-free ldmatrix
#define BPAD 8              // B row stride = 72 elems (144B) -> conflict-free ldmatrix

// m-block bookkeeping: experts <= 8192/128 + 8 = 72 blocks, shared = 32 -> 104
#define MAX_MBLOCKS 104
#define MAX_ROWS    (MAX_MBLOCKS * BM)   // 13312

// ---------------- device scratch ----------------
__device__ int   g_counts[NEXP];
__device__ int   g_fill[NEXP];
__device__ float g_probs[N_TOK * NEXP];
__device__ float g_lse2[N_TOK];
__device__ float g_probs_sum[NEXP];
__device__ float g_zsum;
__device__ int   g_expert_idx[N_TOK * TOPK];
__device__ float g_gate_w[N_TOK * TOPK];
__device__ int   g_row_tok[MAX_ROWS];
__device__ float g_row_w[MAX_ROWS];
__device__ int   g_row_pos[N_TOK * TOPK];
__device__ int   g_seg_start[NEXP + 1];
__device__ int   g_mb_expert[MAX_MBLOCKS];
__device__ int   g_n_mblocks;

// bf16 hi/lo splits. Weights combined as 9 experts (expert 8 = shared).
__device__ __nv_bfloat16 g_x_hi[(size_t)N_TOK * DMODEL];
__device__ __nv_bfloat16 g_x_lo[(size_t)N_TOK * DMODEL];
__device__ __nv_bfloat16 g_w1_hi[(size_t)(NEXP + 1) * DMODEL * HID];
__device__ __nv_bfloat16 g_w1_lo[(size_t)(NEXP + 1) * DMODEL * HID];
__device__ __nv_bfloat16 g_w3_hi[(size_t)(NEXP + 1) * DMODEL * HID];
__device__ __nv_bfloat16 g_w3_lo[(size_t)(NEXP + 1) * DMODEL * HID];
__device__ __nv_bfloat16 g_w2_hi[(size_t)(NEXP + 1) * HID * DMODEL];
__device__ __nv_bfloat16 g_w2_lo[(size_t)(NEXP + 1) * HID * DMODEL];
__device__ __nv_bfloat16 g_h_hi[(size_t)MAX_ROWS * HID];
__device__ __nv_bfloat16 g_h_lo[(size_t)MAX_ROWS * HID];
__device__ float         g_ro[(size_t)MAX_ROWS * DMODEL];

// ---------------- mma helpers ----------------
__device__ __forceinline__ uint32_t smaddr(const void* p) {
    return (uint32_t)__cvta_generic_to_shared(p);
}
__device__ __forceinline__ void ldsm4(uint32_t& r0, uint32_t& r1, uint32_t& r2, uint32_t& r3, uint32_t a) {
    asm volatile("ldmatrix.sync.aligned.m8n8.x4.shared.b16 {%0,%1,%2,%3},[%4];"
                 : "=r"(r0), "=r"(r1), "=r"(r2), "=r"(r3) : "r"(a));
}
__device__ __forceinline__ void ldsm4t(uint32_t& r0, uint32_t& r1, uint32_t& r2, uint32_t& r3, uint32_t a) {
    asm volatile("ldmatrix.sync.aligned.m8n8.x4.trans.shared.b16 {%0,%1,%2,%3},[%4];"
                 : "=r"(r0), "=r"(r1), "=r"(r2), "=r"(r3) : "r"(a));
}
__device__ __forceinline__ void mma16816(float* c, const uint32_t* a, uint32_t b0, uint32_t b1) {
    asm volatile("mma.sync.aligned.m16n8k16.row.col.f32.bf16.bf16.f32 "
                 "{%0,%1,%2,%3},{%4,%5,%6,%7},{%8,%9},{%0,%1,%2,%3};"
                 : "+f"(c[0]), "+f"(c[1]), "+f"(c[2]), "+f"(c[3])
                 : "r"(a[0]), "r"(a[1]), "r"(a[2]), "r"(a[3]), "r"(b0), "r"(b1));
}

// ---------------- init ----------------
__global__ void init_kernel() {
    int i = blockIdx.x * blockDim.x + threadIdx.x;
    if (i < MAX_ROWS) g_row_tok[i] = -1;
    if (i < NEXP) { g_counts[i] = 0; g_fill[i] = 0; }
    if (i == 0) g_zsum = 0.0f;
}

// ---------------- fp32 -> bf16 hi/lo split ----------------
__global__ __launch_bounds__(256) void split_kernel(const float* __restrict__ in,
                                                    __nv_bfloat16* __restrict__ hi,
                                                    __nv_bfloat16* __restrict__ lo, int n) {
    int i = (blockIdx.x * blockDim.x + threadIdx.x) * 4;
    if (i >= n) return;
    float4 v = *(const float4*)(in + i);
    __nv_bfloat16 h0 = __float2bfloat16(v.x);
    __nv_bfloat16 h1 = __float2bfloat16(v.y);
    __nv_bfloat16 h2 = __float2bfloat16(v.z);
    __nv_bfloat16 h3 = __float2bfloat16(v.w);
    __nv_bfloat16 l0 = __float2bfloat16(v.x - __bfloat162float(h0));
    __nv_bfloat16 l1 = __float2bfloat16(v.y - __bfloat162float(h1));
    __nv_bfloat16 l2 = __float2bfloat16(v.z - __bfloat162float(h2));
    __nv_bfloat16 l3 = __float2bfloat16(v.w - __bfloat162float(h3));
    *(__nv_bfloat162*)(hi + i)     = __nv_bfloat162(h0, h1);
    *(__nv_bfloat162*)(hi + i + 2) = __nv_bfloat162(h2, h3);
    *(__nv_bfloat162*)(lo + i)     = __nv_bfloat162(l0, l1);
    *(__nv_bfloat162*)(lo + i + 2) = __nv_bfloat162(l2, l3);
}

// ---------------- router ----------------
__global__ __launch_bounds__(128) void router_kernel(const float* __restrict__ x,
                                                     const float* __restrict__ wr) {
    int tok = blockIdx.x;
    int tid = threadIdx.x;
    const float* xr = x + (size_t)tok * DMODEL;

    float acc[NEXP];
#pragma unroll
    for (int e = 0; e < NEXP; e++) acc[e] = 0.0f;

    for (int d = tid; d < DMODEL; d += 128) {
        float xv = xr[d];
        const float4* w4 = (const float4*)(wr + (size_t)d * NEXP);
        float4 w0 = w4[0];
        float4 w1 = w4[1];
        acc[0] += xv * w0.x; acc[1] += xv * w0.y;
        acc[2] += xv * w0.z; acc[3] += xv * w0.w;
        acc[4] += xv * w1.x; acc[5] += xv * w1.y;
        acc[6] += xv * w1.z; acc[7] += xv * w1.w;
    }
#pragma unroll
    for (int off = 16; off > 0; off >>= 1)
#pragma unroll
        for (int e = 0; e < NEXP; e++)
            acc[e] += __shfl_down_sync(0xffffffffu, acc[e], off);

    __shared__ float s[4][NEXP];
    int w = tid >> 5, l = tid & 31;
    if (l == 0)
#pragma unroll
        for (int e = 0; e < NEXP; e++) s[w][e] = acc[e];
    __syncthreads();

    if (tid == 0) {
        float lg[NEXP];
#pragma unroll
        for (int e = 0; e < NEXP; e++)
            lg[e] = s[0][e] + s[1][e] + s[2][e] + s[3][e];
        float mx = lg[0];
#pragma unroll
        for (int e = 1; e < NEXP; e++) mx = fmaxf(mx, lg[e]);
        float p[NEXP], se = 0.0f;
#pragma unroll
        for (int e = 0; e < NEXP; e++) { p[e] = expf(lg[e] - mx); se += p[e]; }
        float inv = 1.0f / se;
#pragma unroll
        for (int e = 0; e < NEXP; e++) p[e] *= inv;
        float lse = mx + logf(se);

        int b0 = 0;
#pragma unroll
        for (int e = 1; e < NEXP; e++) if (lg[e] > lg[b0]) b0 = e;
        int b1 = (b0 == 0) ? 1 : 0;
#pragma unroll
        for (int e = 0; e < NEXP; e++)
            if (e != b0 && lg[e] > lg[b1]) b1 = e;

        g_expert_idx[tok * 2 + 0] = b0;
        g_expert_idx[tok * 2 + 1] = b1;
        g_gate_w[tok * 2 + 0] = p[b0];
        g_gate_w[tok * 2 + 1] = p[b1];
        atomicAdd(&g_counts[b0], 1);
        atomicAdd(&g_counts[b1], 1);
#pragma unroll
        for (int e = 0; e < NEXP; e++) g_probs[(size_t)tok * NEXP + e] = p[e];
        g_lse2[tok] = lse * lse;
    }
}

// ---------------- deterministic loss reductions ----------------
__global__ __launch_bounds__(256) void reduce_kernel() {
    int which = blockIdx.x;
    int tid = threadIdx.x;
    float s = 0.0f;
    if (which < NEXP) {
        for (int i = tid; i < N_TOK; i += 256) s += g_probs[(size_t)i * NEXP + which];
    } else {
        for (int i = tid; i < N_TOK; i += 256) s += g_lse2[i];
    }
#pragma unroll
    for (int off = 16; off > 0; off >>= 1)
        s += __shfl_down_sync(0xffffffffu, s, off);
    __shared__ float sm[8];
    if ((tid & 31) == 0) sm[tid >> 5] = s;
    __syncthreads();
    if (tid == 0) {
        float t = 0.0f;
#pragma unroll
        for (int i = 0; i < 8; i++) t += sm[i];
        if (which < NEXP) g_probs_sum[which] = t;
        else g_zsum = t;
    }
}

// ---------------- plan: 128-aligned per-expert segments (expert 8 = shared) ----------------
__global__ void plan_kernel() {
    if (threadIdx.x == 0 && blockIdx.x == 0) {
        int acc = 0;
        for (int e = 0; e <= NEXP; e++) {
            int c = (e < NEXP) ? g_counts[e] : N_TOK;
            g_seg_start[e] = acc;
            int nmb = (c + BM - 1) / BM;
            int b0 = acc / BM;
            for (int i = 0; i < nmb; i++) g_mb_expert[b0 + i] = e;
            acc += nmb * BM;
        }
        g_n_mblocks = acc / BM;
    }
}

// ---------------- scatter ----------------
__global__ void scatter_kernel() {
    int tok = blockIdx.x * blockDim.x + threadIdx.x;
    if (tok >= N_TOK) return;
#pragma unroll
    for (int k = 0; k < TOPK; k++) {
        int e = g_expert_idx[tok * 2 + k];
        int p = g_seg_start[e] + atomicAdd(&g_fill[e], 1);
        g_row_tok[p] = tok;
        g_row_w[p] = g_gate_w[tok * 2 + k] * ((float)TOPK / (float)(TOPK + 1));
        g_row_pos[tok * 2 + k] = p;
    }
    int ps = g_seg_start[NEXP] + tok;
    g_row_tok[ps] = tok;
    g_row_w[ps] = 1.0f / (float)(TOPK + 1);
}

// ---------------- stage 1: h = silu(X@W1) * (X@W3)  [bf16x3 mma] ----------------
__global__ __launch_bounds__(256, 1) void stage1_kernel() {
    int mb = blockIdx.x;
    if (mb >= g_n_mblocks) return;
    int e = g_mb_expert[mb];
    const __nv_bfloat16* W1h = g_w1_hi + (size_t)e * DMODEL * HID;
    const __nv_bfloat16* W1l = g_w1_lo + (size_t)e * DMODEL * HID;
    const __nv_bfloat16* W3h = g_w3_hi + (size_t)e * DMODEL * HID;
    const __nv_bfloat16* W3l = g_w3_lo + (size_t)e * DMODEL * HID;
    int row0 = mb * BM;
    int n0 = blockIdx.y * BN;

    __shared__ __nv_bfloat16 sAh[BM][BK + APAD];
    __shared__ __nv_bfloat16 sAl[BM][BK + APAD];
    __shared__ __nv_bfloat16 sB[4][BK][BN + BPAD];   // 0=W1h 1=W1l 2=W3h 3=W3l
    __shared__ int toks[BM];

    int tid = threadIdx.x, lane = tid & 31, warp = tid >> 5;
    if (tid < BM) toks[tid] = g_row_tok[row0 + tid];
    __syncthreads();

    int wm = warp >> 1, wn = warp & 1;

    float accg[2][4][4], accu[2][4][4];
#pragma unroll
    for (int mi = 0; mi < 2; mi++)
#pragma unroll
        for (int ni = 0; ni < 4; ni++)
#pragma unroll
            for (int q = 0; q < 4; q++) { accg[mi][ni][q] = 0.0f; accu[mi][ni][q] = 0.0f; }

    int ar = tid >> 2, ac = (tid & 3) * 8;
    int br = tid >> 3, bc = (tid & 7) * 8;
    int tok0 = toks[ar];
    int tok1 = toks[64 + ar];

    for (int kk = 0; kk < DMODEL; kk += BK) {
        uint4 z = make_uint4(0u, 0u, 0u, 0u);
        uint4 vh0 = z, vl0 = z, vh1 = z, vl1 = z;
        if (tok0 >= 0) {
            vh0 = *(const uint4*)&g_x_hi[(size_t)tok0 * DMODEL + kk + ac];
            vl0 = *(const uint4*)&g_x_lo[(size_t)tok0 * DMODEL + kk + ac];
        }
        if (tok1 >= 0) {
            vh1 = *(const uint4*)&g_x_hi[(size_t)tok1 * DMODEL + kk + ac];
            vl1 = *(const uint4*)&g_x_lo[(size_t)tok1 * DMODEL + kk + ac];
        }
        *(uint4*)&sAh[ar][ac] = vh0;
        *(uint4*)&sAl[ar][ac] = vl0;
        *(uint4*)&sAh[64 + ar][ac] = vh1;
        *(uint4*)&sAl[64 + ar][ac] = vl1;

        size_t bo = (size_t)(kk + br) * HID + n0 + bc;
        *(uint4*)&sB[0][br][bc] = *(const uint4*)&W1h[bo];
        *(uint4*)&sB[1][br][bc] = *(const uint4*)&W1l[bo];
        *(uint4*)&sB[2][br][bc] = *(const uint4*)&W3h[bo];
        *(uint4*)&sB[3][br][bc] = *(const uint4*)&W3l[bo];
        __syncthreads();

#pragma unroll
        for (int ks = 0; ks < 2; ks++) {
            int k0 = ks * 16;
            uint32_t ah[2][4], al[2][4];
#pragma unroll
            for (int mi = 0; mi < 2; mi++) {
                int arow = wm * 32 + mi * 16 + (lane & 15);
                int acol = k0 + (lane >> 4) * 8;
                ldsm4(ah[mi][0], ah[mi][1], ah[mi][2], ah[mi][3], smaddr(&sAh[arow][acol]));
                ldsm4(al[mi][0], al[mi][1], al[mi][2], al[mi][3], smaddr(&sAl[arow][acol]));
            }
            uint32_t bf[4][8];
#pragma unroll
            for (int v = 0; v < 4; v++)
#pragma unroll
                for (int hh = 0; hh < 2; hh++) {
                    int brow = k0 + (lane & 15);
                    int bcol = wn * 32 + hh * 16 + (lane >> 4) * 8;
                    ldsm4t(bf[v][hh * 4 + 0], bf[v][hh * 4 + 1], bf[v][hh * 4 + 2], bf[v][hh * 4 + 3],
                           smaddr(&sB[v][brow][bcol]));
                }
#pragma unroll
            for (int mi = 0; mi < 2; mi++)
#pragma unroll
                for (int ni = 0; ni < 4; ni++) {
                    int rb = (ni >> 1) * 4 + (ni & 1) * 2;
                    mma16816(accg[mi][ni], ah[mi], bf[0][rb], bf[0][rb + 1]);
                    mma16816(accg[mi][ni], ah[mi], bf[1][rb], bf[1][rb + 1]);
                    mma16816(accg[mi][ni], al[mi], bf[0][rb], bf[0][rb + 1]);
                    mma16816(accu[mi][ni], ah[mi], bf[2][rb], bf[2][rb + 1]);
                    mma16816(accu[mi][ni], ah[mi], bf[3][rb], bf[3][rb + 1]);
                    mma16816(accu[mi][ni], al[mi], bf[2][rb], bf[2][rb + 1]);
                }
        }
        __syncthreads();
    }

    // epilogue: SwiGLU + split to bf16 hi/lo
#pragma unroll
    for (int mi = 0; mi < 2; mi++)
#pragma unroll
        for (int ni = 0; ni < 4; ni++) {
            int r = row0 + wm * 32 + mi * 16 + (lane >> 2);
            int c = n0 + wn * 32 + ni * 8 + (lane & 3) * 2;
#pragma unroll
            for (int pr = 0; pr < 2; pr++) {
                int rr = r + pr * 8;
                float g0 = accg[mi][ni][pr * 2 + 0];
                float g1 = accg[mi][ni][pr * 2 + 1];
                float u0 = accu[mi][ni][pr * 2 + 0];
                float u1 = accu[mi][ni][pr * 2 + 1];
                float h0 = g0 / (1.0f + expf(-g0)) * u0;
                float h1 = g1 / (1.0f + expf(-g1)) * u1;
                __nv_bfloat16 h0h = __float2bfloat16(h0);
                __nv_bfloat16 h1h = __float2bfloat16(h1);
                __nv_bfloat16 h0l = __float2bfloat16(h0 - __bfloat162float(h0h));
                __nv_bfloat16 h1l = __float2bfloat16(h1 - __bfloat162float(h1h));
                *(__nv_bfloat162*)&g_h_hi[(size_t)rr * HID + c] = __nv_bfloat162(h0h, h1h);
                *(__nv_bfloat162*)&g_h_lo[(size_t)rr * HID + c] = __nv_bfloat162(h0l, h1l);
            }
        }
}

// ---------------- stage 2: ro = h @ W2  [bf16x3 mma] ----------------
__global__ __launch_bounds__(256, 1) void stage2_kernel() {
    int mb = blockIdx.x;
    if (mb >= g_n_mblocks) return;
    int e = g_mb_expert[mb];
    const __nv_bfloat16* W2h = g_w2_hi + (size_t)e * HID * DMODEL;
    const __nv_bfloat16* W2l = g_w2_lo + (size_t)e * HID * DMODEL;
    int row0 = mb * BM;
    int n0 = blockIdx.y * BN;

    __shared__ __nv_bfloat16 sAh[BM][BK + APAD];
    __shared__ __nv_bfloat16 sAl[BM][BK + APAD];
    __shared__ __nv_bfloat16 sB[2][BK][BN + BPAD];   // 0=W2h 1=W2l

    int tid = threadIdx.x, lane = tid & 31, warp = tid >> 5;
    int wm = warp >> 1, wn = warp & 1;

    float acc[2][4][4];
#pragma unroll
    for (int mi = 0; mi < 2; mi++)
#pragma unroll
        for (int ni = 0; ni < 4; ni++)
#pragma unroll
            for (int q = 0; q < 4; q++) acc[mi][ni][q] = 0.0f;

    int ar = tid >> 2, ac = (tid & 3) * 8;
    int br = tid >> 3, bc = (tid & 7) * 8;

    for (int kk = 0; kk < HID; kk += BK) {
#pragma unroll
        for (int hh = 0; hh < 2; hh++) {
            int r = hh * 64 + ar;
            *(uint4*)&sAh[r][ac] = *(const uint4*)&g_h_hi[(size_t)(row0 + r) * HID + kk + ac];
            *(uint4*)&sAl[r][ac] = *(const uint4*)&g_h_lo[(size_t)(row0 + r) * HID + kk + ac];
        }
        size_t bo = (size_t)(kk + br) * DMODEL + n0 + bc;
        *(uint4*)&sB[0][br][bc] = *(const uint4*)&W2h[bo];
        *(uint4*)&sB[1][br][bc] = *(const uint4*)&W2l[bo];
        __syncthreads();

#pragma unroll
        for (int ks = 0; ks < 2; ks++) {
            int k0 = ks * 16;
            uint32_t ah[2][4], al[2][4];
#pragma unroll
            for (int mi = 0; mi < 2; mi++) {
                int arow = wm * 32 + mi * 16 + (lane & 15);
                int acol = k0 + (lane >> 4) * 8;
                ldsm4(ah[mi][0], ah[mi][1], ah[mi][2], ah[mi][3], smaddr(&sAh[arow][acol]));
                ldsm4(al[mi][0], al[mi][1], al[mi][2], al[mi][3], smaddr(&sAl[arow][acol]));
            }
            uint32_t bf[2][8];
#pragma unroll
            for (int v = 0; v < 2; v++)
#pragma unroll
                for (int hh = 0; hh < 2; hh++) {
                    int brow = k0 + (lane & 15);
                    int bcol = wn * 32 + hh * 16 + (lane >> 4) * 8;
                    ldsm4t(bf[v][hh * 4 + 0], bf[v][hh * 4 + 1], bf[v][hh * 4 + 2], bf[v][hh * 4 + 3],
                           smaddr(&sB[v][brow][bcol]));
                }
#pragma unroll
            for (int mi = 0; mi < 2; mi++)
#pragma unroll
                for (int ni = 0; ni < 4; ni++) {
                    int rb = (ni >> 1) * 4 + (ni & 1) * 2;
                    mma16816(acc[mi][ni], ah[mi], bf[0][rb], bf[0][rb + 1]);
                    mma16816(acc[mi][ni], ah[mi], bf[1][rb], bf[1][rb + 1]);
                    mma16816(acc[mi][ni], al[mi], bf[0][rb], bf[0][rb + 1]);
                }
        }
        __syncthreads();
    }

#pragma unroll
    for (int mi = 0; mi < 2; mi++)
#pragma unroll
        for (int ni = 0; ni < 4; ni++) {
            int r = row0 + wm * 32 + mi * 16 + (lane >> 2);
            int c = n0 + wn * 32 + ni * 8 + (lane & 3) * 2;
#pragma unroll
            for (int pr = 0; pr < 2; pr++) {
                int rr = r + pr * 8;
                float2 o = make_float2(acc[mi][ni][pr * 2 + 0], acc[mi][ni][pr * 2 + 1]);
                *(float2*)&g_ro[(size_t)rr * DMODEL + c] = o;
            }
        }
}

// ---------------- deterministic weighted combine ----------------
__global__ __launch_bounds__(256) void combine_kernel(float* __restrict__ out) {
    int tok = blockIdx.x;
    int p0 = g_row_pos[tok * 2 + 0];
    int p1 = g_row_pos[tok * 2 + 1];
    int ps = g_seg_start[NEXP] + tok;
    float w0 = g_row_w[p0];
    float w1 = g_row_w[p1];
    const float ws = 1.0f / (float)(TOPK + 1);
    for (int d = threadIdx.x; d < DMODEL; d += 256) {
        float v = w0 * g_ro[(size_t)p0 * DMODEL + d]
                + w1 * g_ro[(size_t)p1 * DMODEL + d]
                + ws * g_ro[(size_t)ps * DMODEL + d];
        out[(size_t)tok * DMODEL + d] = v;
    }
}

// ---------------- losses ----------------
__global__ void finalize_kernel(float* __restrict__ out) {
    if (threadIdx.x == 0 && blockIdx.x == 0) {
        float lb = 0.0f;
        for (int e = 0; e < NEXP; e++)
            lb += (float)g_counts[e] * g_probs_sum[e];
        lb *= (float)NEXP * 0.01f / (16.0f * (float)N_TOK * (float)TOPK);
        out[(size_t)N_TOK * DMODEL + 0] = lb;
        out[(size_t)N_TOK * DMODEL + 1] = 0.001f * g_zsum / (float)N_TOK;
    }
}

// ---------------- launch ----------------
extern "C" void kernel_launch(void* const* d_in, const int* in_sizes, int n_in,
                              void* d_out, int out_size) {
    const float* x   = (const float*)d_in[0];
    const float* wr  = (const float*)d_in[1];
    const float* w1  = (const float*)d_in[2];
    const float* w3  = (const float*)d_in[3];
    const float* w2  = (const float*)d_in[4];
    const float* sw1 = (const float*)d_in[5];
    const float* sw3 = (const float*)d_in[6];
    const float* sw2 = (const float*)d_in[7];
    float* out = (float*)d_out;

    // resolve device-scratch addresses for split targets
    __nv_bfloat16 *xh, *xl, *w1h, *w1l, *w3h, *w3l, *w2h, *w2l;
    cudaGetSymbolAddress((void**)&xh,  g_x_hi);
    cudaGetSymbolAddress((void**)&xl,  g_x_lo);
    cudaGetSymbolAddress((void**)&w1h, g_w1_hi);
    cudaGetSymbolAddress((void**)&w1l, g_w1_lo);
    cudaGetSymbolAddress((void**)&w3h, g_w3_hi);
    cudaGetSymbolAddress((void**)&w3l, g_w3_lo);
    cudaGetSymbolAddress((void**)&w2h, g_w2_hi);
    cudaGetSymbolAddress((void**)&w2l, g_w2_lo);

    const int EW = NEXP * DMODEL * HID;      // 8M elems
    const int SW = DMODEL * HID;             // 1M elems
    const int NX = N_TOK * DMODEL;           // 4M elems

    init_kernel<<<(MAX_ROWS + 255) / 256, 256>>>();
    split_kernel<<<(NX / 4 + 255) / 256, 256>>>(x, xh, xl, NX);
    split_kernel<<<(EW / 4 + 255) / 256, 256>>>(w1, w1h, w1l, EW);
    split_kernel<<<(EW / 4 + 255) / 256, 256>>>(w3, w3h, w3l, EW);
    split_kernel<<<(EW / 4 + 255) / 256, 256>>>(w2, w2h, w2l, EW);
    split_kernel<<<(SW / 4 + 255) / 256, 256>>>(sw1, w1h + EW, w1l + EW, SW);
    split_kernel<<<(SW / 4 + 255) / 256, 256>>>(sw3, w3h + EW, w3l + EW, SW);
    split_kernel<<<(SW / 4 + 255) / 256, 256>>>(sw2, w2h + EW, w2l + EW, SW);

    router_kernel<<<N_TOK, 128>>>(x, wr);
    reduce_kernel<<<NEXP + 1, 256>>>();
    plan_kernel<<<1, 32>>>();
    scatter_kernel<<<(N_TOK + 255) / 256, 256>>>();

    stage1_kernel<<<dim3(MAX_MBLOCKS, HID / BN), 256>>>();
    stage2_kernel<<<dim3(MAX_MBLOCKS, DMODEL / BN), 256>>>();
    combine_kernel<<<N_TOK, 256>>>(out);
    finalize_kernel<<<1, 32>>>(out);
}

// round 5
// speedup vs baseline: 2.3159x; 1.2306x over previous
#include <cuda_runtime.h>
#include <cuda_bf16.h>
#include <math.h>
#include <stdint.h>

// ---------------- problem constants ----------------
#define N_TOK   4096
#define DMODEL  1024
#define NEXP    8
#define HID     1024
#define TOPK    2

// GEMM tiling (mma.sync bf16 path)
#define BM 128
#define BN 64
#define BK 32
#define APAD 8              // A row stride = 40 elems (80B), 16B-aligned, conflict-free ldmatrix
#define BPAD 8              // B row stride = 72 elems (144B)
#define ASTR (BK + APAD)
#define BSTR (BN + BPAD)

#define MAX_MBLOCKS 104
#define MAX_ROWS    (MAX_MBLOCKS * BM)   // 13312

// dynamic smem layouts
#define S1_AH_B   (BM * ASTR * 2)                 // 10240
#define S1_B_B    (4 * BK * BSTR * 2)             // 18432
#define S1_STAGE  (2 * S1_AH_B + S1_B_B)          // 38912
#define S1_TOTAL  (512 + 2 * S1_STAGE)            // 78336

#define S2_B_B    (2 * BK * BSTR * 2)             // 9216
#define S2_STAGE  (2 * S1_AH_B + S2_B_B)          // 29696
#define S2_TOTAL  (2 * S2_STAGE)                  // 59392

// ---------------- device scratch ----------------
__device__ int   g_counts[NEXP];
__device__ int   g_fill[NEXP];
__device__ float g_probs[N_TOK * NEXP];
__device__ float g_lse2[N_TOK];
__device__ float g_probs_sum[NEXP];
__device__ float g_zsum;
__device__ int   g_expert_idx[N_TOK * TOPK];
__device__ float g_gate_w[N_TOK * TOPK];
__device__ int   g_row_tok[MAX_ROWS];
__device__ float g_row_w[MAX_ROWS];
__device__ int   g_row_pos[N_TOK * TOPK];
__device__ int   g_seg_start[NEXP + 1];
__device__ int   g_mb_expert[MAX_MBLOCKS];
__device__ int   g_n_mblocks;

__device__ __nv_bfloat16 g_x_hi[(size_t)N_TOK * DMODEL];
__device__ __nv_bfloat16 g_x_lo[(size_t)N_TOK * DMODEL];
__device__ __nv_bfloat16 g_w1_hi[(size_t)(NEXP + 1) * DMODEL * HID];
__device__ __nv_bfloat16 g_w1_lo[(size_t)(NEXP + 1) * DMODEL * HID];
__device__ __nv_bfloat16 g_w3_hi[(size_t)(NEXP + 1) * DMODEL * HID];
__device__ __nv_bfloat16 g_w3_lo[(size_t)(NEXP + 1) * DMODEL * HID];
__device__ __nv_bfloat16 g_w2_hi[(size_t)(NEXP + 1) * HID * DMODEL];
__device__ __nv_bfloat16 g_w2_lo[(size_t)(NEXP + 1) * HID * DMODEL];
__device__ __nv_bfloat16 g_h_hi[(size_t)MAX_ROWS * HID];
__device__ __nv_bfloat16 g_h_lo[(size_t)MAX_ROWS * HID];
__device__ float         g_ro[(size_t)MAX_ROWS * DMODEL];

// ---------------- asm helpers ----------------
__device__ __forceinline__ uint32_t smaddr(const void* p) {
    return (uint32_t)__cvta_generic_to_shared(p);
}
__device__ __forceinline__ void cpa16(uint32_t dst, const void* src, int szbytes) {
    asm volatile("cp.async.cg.shared.global [%0],[%1],16,%2;"
                 :: "r"(dst), "l"(src), "r"(szbytes));
}
__device__ __forceinline__ void cpa_commit() {
    asm volatile("cp.async.commit_group;");
}
template <int N>
__device__ __forceinline__ void cpa_wait() {
    asm volatile("cp.async.wait_group %0;" :: "n"(N));
}
__device__ __forceinline__ void ldsm4(uint32_t& r0, uint32_t& r1, uint32_t& r2, uint32_t& r3, uint32_t a) {
    asm volatile("ldmatrix.sync.aligned.m8n8.x4.shared.b16 {%0,%1,%2,%3},[%4];"
                 : "=r"(r0), "=r"(r1), "=r"(r2), "=r"(r3) : "r"(a));
}
__device__ __forceinline__ void ldsm4t(uint32_t& r0, uint32_t& r1, uint32_t& r2, uint32_t& r3, uint32_t a) {
    asm volatile("ldmatrix.sync.aligned.m8n8.x4.trans.shared.b16 {%0,%1,%2,%3},[%4];"
                 : "=r"(r0), "=r"(r1), "=r"(r2), "=r"(r3) : "r"(a));
}
__device__ __forceinline__ void mma16816(float* c, const uint32_t* a, uint32_t b0, uint32_t b1) {
    asm volatile("mma.sync.aligned.m16n8k16.row.col.f32.bf16.bf16.f32 "
                 "{%0,%1,%2,%3},{%4,%5,%6,%7},{%8,%9},{%0,%1,%2,%3};"
                 : "+f"(c[0]), "+f"(c[1]), "+f"(c[2]), "+f"(c[3])
                 : "r"(a[0]), "r"(a[1]), "r"(a[2]), "r"(a[3]), "r"(b0), "r"(b1));
}

// ---------------- init ----------------
__global__ void init_kernel() {
    int i = blockIdx.x * blockDim.x + threadIdx.x;
    if (i < MAX_ROWS) g_row_tok[i] = -1;
    if (i < NEXP) { g_counts[i] = 0; g_fill[i] = 0; }
    if (i == 0) g_zsum = 0.0f;
}

// ---------------- fp32 -> bf16 hi/lo split ----------------
__global__ __launch_bounds__(256) void split_kernel(const float* __restrict__ in,
                                                    __nv_bfloat16* __restrict__ hi,
                                                    __nv_bfloat16* __restrict__ lo, int n) {
    int i = (blockIdx.x * blockDim.x + threadIdx.x) * 4;
    if (i >= n) return;
    float4 v = *(const float4*)(in + i);
    __nv_bfloat16 h0 = __float2bfloat16(v.x);
    __nv_bfloat16 h1 = __float2bfloat16(v.y);
    __nv_bfloat16 h2 = __float2bfloat16(v.z);
    __nv_bfloat16 h3 = __float2bfloat16(v.w);
    __nv_bfloat16 l0 = __float2bfloat16(v.x - __bfloat162float(h0));
    __nv_bfloat16 l1 = __float2bfloat16(v.y - __bfloat162float(h1));
    __nv_bfloat16 l2 = __float2bfloat16(v.z - __bfloat162float(h2));
    __nv_bfloat16 l3 = __float2bfloat16(v.w - __bfloat162float(h3));
    *(__nv_bfloat162*)(hi + i)     = __nv_bfloat162(h0, h1);
    *(__nv_bfloat162*)(hi + i + 2) = __nv_bfloat162(h2, h3);
    *(__nv_bfloat162*)(lo + i)     = __nv_bfloat162(l0, l1);
    *(__nv_bfloat162*)(lo + i + 2) = __nv_bfloat162(l2, l3);
}

// ---------------- router ----------------
__global__ __launch_bounds__(128) void router_kernel(const float* __restrict__ x,
                                                     const float* __restrict__ wr) {
    int tok = blockIdx.x;
    int tid = threadIdx.x;
    const float* xr = x + (size_t)tok * DMODEL;

    float acc[NEXP];
#pragma unroll
    for (int e = 0; e < NEXP; e++) acc[e] = 0.0f;

    for (int d = tid; d < DMODEL; d += 128) {
        float xv = xr[d];
        const float4* w4 = (const float4*)(wr + (size_t)d * NEXP);
        float4 w0 = w4[0];
        float4 w1 = w4[1];
        acc[0] += xv * w0.x; acc[1] += xv * w0.y;
        acc[2] += xv * w0.z; acc[3] += xv * w0.w;
        acc[4] += xv * w1.x; acc[5] += xv * w1.y;
        acc[6] += xv * w1.z; acc[7] += xv * w1.w;
    }
#pragma unroll
    for (int off = 16; off > 0; off >>= 1)
#pragma unroll
        for (int e = 0; e < NEXP; e++)
            acc[e] += __shfl_down_sync(0xffffffffu, acc[e], off);

    __shared__ float s[4][NEXP];
    int w = tid >> 5, l = tid & 31;
    if (l == 0)
#pragma unroll
        for (int e = 0; e < NEXP; e++) s[w][e] = acc[e];
    __syncthreads();

    if (tid == 0) {
        float lg[NEXP];
#pragma unroll
        for (int e = 0; e < NEXP; e++)
            lg[e] = s[0][e] + s[1][e] + s[2][e] + s[3][e];
        float mx = lg[0];
#pragma unroll
        for (int e = 1; e < NEXP; e++) mx = fmaxf(mx, lg[e]);
        float p[NEXP], se = 0.0f;
#pragma unroll
        for (int e = 0; e < NEXP; e++) { p[e] = expf(lg[e] - mx); se += p[e]; }
        float inv = 1.0f / se;
#pragma unroll
        for (int e = 0; e < NEXP; e++) p[e] *= inv;
        float lse = mx + logf(se);

        int b0 = 0;
#pragma unroll
        for (int e = 1; e < NEXP; e++) if (lg[e] > lg[b0]) b0 = e;
        int b1 = (b0 == 0) ? 1 : 0;
#pragma unroll
        for (int e = 0; e < NEXP; e++)
            if (e != b0 && lg[e] > lg[b1]) b1 = e;

        g_expert_idx[tok * 2 + 0] = b0;
        g_expert_idx[tok * 2 + 1] = b1;
        g_gate_w[tok * 2 + 0] = p[b0];
        g_gate_w[tok * 2 + 1] = p[b1];
        atomicAdd(&g_counts[b0], 1);
        atomicAdd(&g_counts[b1], 1);
#pragma unroll
        for (int e = 0; e < NEXP; e++) g_probs[(size_t)tok * NEXP + e] = p[e];
        g_lse2[tok] = lse * lse;
    }
}

// ---------------- deterministic loss reductions ----------------
__global__ __launch_bounds__(256) void reduce_kernel() {
    int which = blockIdx.x;
    int tid = threadIdx.x;
    float s = 0.0f;
    if (which < NEXP) {
        for (int i = tid; i < N_TOK; i += 256) s += g_probs[(size_t)i * NEXP + which];
    } else {
        for (int i = tid; i < N_TOK; i += 256) s += g_lse2[i];
    }
#pragma unroll
    for (int off = 16; off > 0; off >>= 1)
        s += __shfl_down_sync(0xffffffffu, s, off);
    __shared__ float sm[8];
    if ((tid & 31) == 0) sm[tid >> 5] = s;
    __syncthreads();
    if (tid == 0) {
        float t = 0.0f;
#pragma unroll
        for (int i = 0; i < 8; i++) t += sm[i];
        if (which < NEXP) g_probs_sum[which] = t;
        else g_zsum = t;
    }
}

// ---------------- plan ----------------
__global__ void plan_kernel() {
    if (threadIdx.x == 0 && blockIdx.x == 0) {
        int acc = 0;
        for (int e = 0; e <= NEXP; e++) {
            int c = (e < NEXP) ? g_counts[e] : N_TOK;
            g_seg_start[e] = acc;
            int nmb = (c + BM - 1) / BM;
            int b0 = acc / BM;
            for (int i = 0; i < nmb; i++) g_mb_expert[b0 + i] = e;
            acc += nmb * BM;
        }
        g_n_mblocks = acc / BM;
    }
}

// ---------------- scatter ----------------
__global__ void scatter_kernel() {
    int tok = blockIdx.x * blockDim.x + threadIdx.x;
    if (tok >= N_TOK) return;
#pragma unroll
    for (int k = 0; k < TOPK; k++) {
        int e = g_expert_idx[tok * 2 + k];
        int p = g_seg_start[e] + atomicAdd(&g_fill[e], 1);
        g_row_tok[p] = tok;
        g_row_w[p] = g_gate_w[tok * 2 + k] * ((float)TOPK / (float)(TOPK + 1));
        g_row_pos[tok * 2 + k] = p;
    }
    int ps = g_seg_start[NEXP] + tok;
    g_row_tok[ps] = tok;
    g_row_w[ps] = 1.0f / (float)(TOPK + 1);
}

// ---------------- stage 1: h = silu(X@W1) * (X@W3)  [bf16x3 mma + cp.async pipeline] ----------------
__global__ __launch_bounds__(256, 1) void stage1_kernel() {
    int mb = blockIdx.x;
    if (mb >= g_n_mblocks) return;
    int e = g_mb_expert[mb];
    const __nv_bfloat16* W1h = g_w1_hi + (size_t)e * DMODEL * HID;
    const __nv_bfloat16* W1l = g_w1_lo + (size_t)e * DMODEL * HID;
    const __nv_bfloat16* W3h = g_w3_hi + (size_t)e * DMODEL * HID;
    const __nv_bfloat16* W3l = g_w3_lo + (size_t)e * DMODEL * HID;
    int row0 = mb * BM;
    int n0 = blockIdx.y * BN;

    extern __shared__ char dsm[];
    int* toks = (int*)dsm;
    char* base = dsm + 512;

    int tid = threadIdx.x, lane = tid & 31, warp = tid >> 5;
    if (tid < BM) toks[tid] = g_row_tok[row0 + tid];
    __syncthreads();

    int wm = warp >> 1, wn = warp & 1;

    float accg[2][4][4], accu[2][4][4];
#pragma unroll
    for (int mi = 0; mi < 2; mi++)
#pragma unroll
        for (int ni = 0; ni < 4; ni++)
#pragma unroll
            for (int q = 0; q < 4; q++) { accg[mi][ni][q] = 0.0f; accu[mi][ni][q] = 0.0f; }

    int ar = tid >> 2, ac = (tid & 3) * 8;
    int br = tid >> 3, bc = (tid & 7) * 8;
    int tok0 = toks[ar];
    int tok1 = toks[64 + ar];
    int sz0 = (tok0 >= 0) ? 16 : 0;
    int sz1 = (tok1 >= 0) ? 16 : 0;
    size_t xb0 = (tok0 >= 0) ? ((size_t)tok0 * DMODEL + ac) : 0;
    size_t xb1 = (tok1 >= 0) ? ((size_t)tok1 * DMODEL + ac) : 0;

    const int NIT = DMODEL / BK;

    auto issue = [&](int it, int buf) {
        char* st = base + buf * S1_STAGE;
        __nv_bfloat16* sAh = (__nv_bfloat16*)st;
        __nv_bfloat16* sAl = sAh + BM * ASTR;
        __nv_bfloat16* sB  = sAl + BM * ASTR;
        int kk = it * BK;
        cpa16(smaddr(&sAh[ar * ASTR + ac]),        &g_x_hi[xb0 + kk], sz0);
        cpa16(smaddr(&sAl[ar * ASTR + ac]),        &g_x_lo[xb0 + kk], sz0);
        cpa16(smaddr(&sAh[(64 + ar) * ASTR + ac]), &g_x_hi[xb1 + kk], sz1);
        cpa16(smaddr(&sAl[(64 + ar) * ASTR + ac]), &g_x_lo[xb1 + kk], sz1);
        size_t bo = (size_t)(kk + br) * HID + n0 + bc;
        cpa16(smaddr(&sB[(0 * BK + br) * BSTR + bc]), &W1h[bo], 16);
        cpa16(smaddr(&sB[(1 * BK + br) * BSTR + bc]), &W1l[bo], 16);
        cpa16(smaddr(&sB[(2 * BK + br) * BSTR + bc]), &W3h[bo], 16);
        cpa16(smaddr(&sB[(3 * BK + br) * BSTR + bc]), &W3l[bo], 16);
        cpa_commit();
    };

    issue(0, 0);

    for (int it = 0; it < NIT; it++) {
        int buf = it & 1;
        if (it + 1 < NIT) { issue(it + 1, buf ^ 1); cpa_wait<1>(); }
        else              { cpa_wait<0>(); }
        __syncthreads();

        char* st = base + buf * S1_STAGE;
        __nv_bfloat16* sAh = (__nv_bfloat16*)st;
        __nv_bfloat16* sAl = sAh + BM * ASTR;
        __nv_bfloat16* sB  = sAl + BM * ASTR;

#pragma unroll
        for (int ks = 0; ks < 2; ks++) {
            int k0 = ks * 16;
            uint32_t ah[2][4], al[2][4];
#pragma unroll
            for (int mi = 0; mi < 2; mi++) {
                int arow = wm * 32 + mi * 16 + (lane & 15);
                int acol = k0 + (lane >> 4) * 8;
                ldsm4(ah[mi][0], ah[mi][1], ah[mi][2], ah[mi][3], smaddr(&sAh[arow * ASTR + acol]));
                ldsm4(al[mi][0], al[mi][1], al[mi][2], al[mi][3], smaddr(&sAl[arow * ASTR + acol]));
            }
            uint32_t bf[4][8];
#pragma unroll
            for (int v = 0; v < 4; v++)
#pragma unroll
                for (int hh = 0; hh < 2; hh++) {
                    int brow = k0 + (lane & 15);
                    int bcol = wn * 32 + hh * 16 + (lane >> 4) * 8;
                    ldsm4t(bf[v][hh * 4 + 0], bf[v][hh * 4 + 1], bf[v][hh * 4 + 2], bf[v][hh * 4 + 3],
                           smaddr(&sB[(v * BK + brow) * BSTR + bcol]));
                }
#pragma unroll
            for (int mi = 0; mi < 2; mi++)
#pragma unroll
                for (int ni = 0; ni < 4; ni++) {
                    int rb = (ni >> 1) * 4 + (ni & 1) * 2;
                    mma16816(accg[mi][ni], ah[mi], bf[0][rb], bf[0][rb + 1]);
                    mma16816(accg[mi][ni], ah[mi], bf[1][rb], bf[1][rb + 1]);
                    mma16816(accg[mi][ni], al[mi], bf[0][rb], bf[0][rb + 1]);
                    mma16816(accu[mi][ni], ah[mi], bf[2][rb], bf[2][rb + 1]);
                    mma16816(accu[mi][ni], ah[mi], bf[3][rb], bf[3][rb + 1]);
                    mma16816(accu[mi][ni], al[mi], bf[2][rb], bf[2][rb + 1]);
                }
        }
        __syncthreads();
    }

    // epilogue: SwiGLU + split to bf16 hi/lo
#pragma unroll
    for (int mi = 0; mi < 2; mi++)
#pragma unroll
        for (int ni = 0; ni < 4; ni++) {
            int r = row0 + wm * 32 + mi * 16 + (lane >> 2);
            int c = n0 + wn * 32 + ni * 8 + (lane & 3) * 2;
#pragma unroll
            for (int pr = 0; pr < 2; pr++) {
                int rr = r + pr * 8;
                float g0 = accg[mi][ni][pr * 2 + 0];
                float g1 = accg[mi][ni][pr * 2 + 1];
                float u0 = accu[mi][ni][pr * 2 + 0];
                float u1 = accu[mi][ni][pr * 2 + 1];
                float h0 = g0 / (1.0f + expf(-g0)) * u0;
                float h1 = g1 / (1.0f + expf(-g1)) * u1;
                __nv_bfloat16 h0h = __float2bfloat16(h0);
                __nv_bfloat16 h1h = __float2bfloat16(h1);
                __nv_bfloat16 h0l = __float2bfloat16(h0 - __bfloat162float(h0h));
                __nv_bfloat16 h1l = __float2bfloat16(h1 - __bfloat162float(h1h));
                *(__nv_bfloat162*)&g_h_hi[(size_t)rr * HID + c] = __nv_bfloat162(h0h, h1h);
                *(__nv_bfloat162*)&g_h_lo[(size_t)rr * HID + c] = __nv_bfloat162(h0l, h1l);
            }
        }
}

// ---------------- stage 2: ro = h @ W2  [bf16x3 mma + cp.async pipeline] ----------------
__global__ __launch_bounds__(256, 1) void stage2_kernel() {
    int mb = blockIdx.x;
    if (mb >= g_n_mblocks) return;
    int e = g_mb_expert[mb];
    const __nv_bfloat16* W2h = g_w2_hi + (size_t)e * HID * DMODEL;
    const __nv_bfloat16* W2l = g_w2_lo + (size_t)e * HID * DMODEL;
    int row0 = mb * BM;
    int n0 = blockIdx.y * BN;

    extern __shared__ char dsm[];
    char* base = dsm;

    int tid = threadIdx.x, lane = tid & 31, warp = tid >> 5;
    int wm = warp >> 1, wn = warp & 1;

    float acc[2][4][4];
#pragma unroll
    for (int mi = 0; mi < 2; mi++)
#pragma unroll
        for (int ni = 0; ni < 4; ni++)
#pragma unroll
            for (int q = 0; q < 4; q++) acc[mi][ni][q] = 0.0f;

    int ar = tid >> 2, ac = (tid & 3) * 8;
    int br = tid >> 3, bc = (tid & 7) * 8;

    const int NIT = HID / BK;

    auto issue = [&](int it, int buf) {
        char* st = base + buf * S2_STAGE;
        __nv_bfloat16* sAh = (__nv_bfloat16*)st;
        __nv_bfloat16* sAl = sAh + BM * ASTR;
        __nv_bfloat16* sB  = sAl + BM * ASTR;
        int kk = it * BK;
#pragma unroll
        for (int hh = 0; hh < 2; hh++) {
            int r = hh * 64 + ar;
            size_t ao = (size_t)(row0 + r) * HID + kk + ac;
            cpa16(smaddr(&sAh[r * ASTR + ac]), &g_h_hi[ao], 16);
            cpa16(smaddr(&sAl[r * ASTR + ac]), &g_h_lo[ao], 16);
        }
        size_t bo = (size_t)(kk + br) * DMODEL + n0 + bc;
        cpa16(smaddr(&sB[(0 * BK + br) * BSTR + bc]), &W2h[bo], 16);
        cpa16(smaddr(&sB[(1 * BK + br) * BSTR + bc]), &W2l[bo], 16);
        cpa_commit();
    };

    issue(0, 0);

    for (int it = 0; it < NIT; it++) {
        int buf = it & 1;
        if (it + 1 < NIT) { issue(it + 1, buf ^ 1); cpa_wait<1>(); }
        else              { cpa_wait<0>(); }
        __syncthreads();

        char* st = base + buf * S2_STAGE;
        __nv_bfloat16* sAh = (__nv_bfloat16*)st;
        __nv_bfloat16* sAl = sAh + BM * ASTR;
        __nv_bfloat16* sB  = sAl + BM * ASTR;

#pragma unroll
        for (int ks = 0; ks < 2; ks++) {
            int k0 = ks * 16;
            uint32_t ah[2][4], al[2][4];
#pragma unroll
            for (int mi = 0; mi < 2; mi++) {
                int arow = wm * 32 + mi * 16 + (lane & 15);
                int acol = k0 + (lane >> 4) * 8;
                ldsm4(ah[mi][0], ah[mi][1], ah[mi][2], ah[mi][3], smaddr(&sAh[arow * ASTR + acol]));
                ldsm4(al[mi][0], al[mi][1], al[mi][2], al[mi][3], smaddr(&sAl[arow * ASTR + acol]));
            }
            uint32_t bf[2][8];
#pragma unroll
            for (int v = 0; v < 2; v++)
#pragma unroll
                for (int hh = 0; hh < 2; hh++) {
                    int brow = k0 + (lane & 15);
                    int bcol = wn * 32 + hh * 16 + (lane >> 4) * 8;
                    ldsm4t(bf[v][hh * 4 + 0], bf[v][hh * 4 + 1], bf[v][hh * 4 + 2], bf[v][hh * 4 + 3],
                           smaddr(&sB[(v * BK + brow) * BSTR + bcol]));
                }
#pragma unroll
            for (int mi = 0; mi < 2; mi++)
#pragma unroll
                for (int ni = 0; ni < 4; ni++) {
                    int rb = (ni >> 1) * 4 + (ni & 1) * 2;
                    mma16816(acc[mi][ni], ah[mi], bf[0][rb], bf[0][rb + 1]);
                    mma16816(acc[mi][ni], ah[mi], bf[1][rb], bf[1][rb + 1]);
                    mma16816(acc[mi][ni], al[mi], bf[0][rb], bf[0][rb + 1]);
                }
        }
        __syncthreads();
    }

#pragma unroll
    for (int mi = 0; mi < 2; mi++)
#pragma unroll
        for (int ni = 0; ni < 4; ni++) {
            int r = row0 + wm * 32 + mi * 16 + (lane >> 2);
            int c = n0 + wn * 32 + ni * 8 + (lane & 3) * 2;
#pragma unroll
            for (int pr = 0; pr < 2; pr++) {
                int rr = r + pr * 8;
                float2 o = make_float2(acc[mi][ni][pr * 2 + 0], acc[mi][ni][pr * 2 + 1]);
                *(float2*)&g_ro[(size_t)rr * DMODEL + c] = o;
            }
        }
}

// ---------------- deterministic weighted combine ----------------
__global__ __launch_bounds__(256) void combine_kernel(float* __restrict__ out) {
    int tok = blockIdx.x;
    int p0 = g_row_pos[tok * 2 + 0];
    int p1 = g_row_pos[tok * 2 + 1];
    int ps = g_seg_start[NEXP] + tok;
    float w0 = g_row_w[p0];
    float w1 = g_row_w[p1];
    const float ws = 1.0f / (float)(TOPK + 1);
    for (int d = threadIdx.x; d < DMODEL; d += 256) {
        float v = w0 * g_ro[(size_t)p0 * DMODEL + d]
                + w1 * g_ro[(size_t)p1 * DMODEL + d]
                + ws * g_ro[(size_t)ps * DMODEL + d];
        out[(size_t)tok * DMODEL + d] = v;
    }
}

// ---------------- losses ----------------
__global__ void finalize_kernel(float* __restrict__ out) {
    if (threadIdx.x == 0 && blockIdx.x == 0) {
        float lb = 0.0f;
        for (int e = 0; e < NEXP; e++)
            lb += (float)g_counts[e] * g_probs_sum[e];
        lb *= (float)NEXP * 0.01f / (16.0f * (float)N_TOK * (float)TOPK);
        out[(size_t)N_TOK * DMODEL + 0] = lb;
        out[(size_t)N_TOK * DMODEL + 1] = 0.001f * g_zsum / (float)N_TOK;
    }
}

// ---------------- launch ----------------
extern "C" void kernel_launch(void* const* d_in, const int* in_sizes, int n_in,
                              void* d_out, int out_size) {
    const float* x   = (const float*)d_in[0];
    const float* wr  = (const float*)d_in[1];
    const float* w1  = (const float*)d_in[2];
    const float* w3  = (const float*)d_in[3];
    const float* w2  = (const float*)d_in[4];
    const float* sw1 = (const float*)d_in[5];
    const float* sw3 = (const float*)d_in[6];
    const float* sw2 = (const float*)d_in[7];
    float* out = (float*)d_out;

    static int s_attr_done = 0;
    if (!s_attr_done) {
        cudaFuncSetAttribute(stage1_kernel, cudaFuncAttributeMaxDynamicSharedMemorySize, S1_TOTAL);
        cudaFuncSetAttribute(stage2_kernel, cudaFuncAttributeMaxDynamicSharedMemorySize, S2_TOTAL);
        s_attr_done = 1;
    }

    __nv_bfloat16 *xh, *xl, *w1h, *w1l, *w3h, *w3l, *w2h, *w2l;
    cudaGetSymbolAddress((void**)&xh,  g_x_hi);
    cudaGetSymbolAddress((void**)&xl,  g_x_lo);
    cudaGetSymbolAddress((void**)&w1h, g_w1_hi);
    cudaGetSymbolAddress((void**)&w1l, g_w1_lo);
    cudaGetSymbolAddress((void**)&w3h, g_w3_hi);
    cudaGetSymbolAddress((void**)&w3l, g_w3_lo);
    cudaGetSymbolAddress((void**)&w2h, g_w2_hi);
    cudaGetSymbolAddress((void**)&w2l, g_w2_lo);

    const int EW = NEXP * DMODEL * HID;
    const int SW = DMODEL * HID;
    const int NX = N_TOK * DMODEL;

    init_kernel<<<(MAX_ROWS + 255) / 256, 256>>>();
    split_kernel<<<(NX / 4 + 255) / 256, 256>>>(x, xh, xl, NX);
    split_kernel<<<(EW / 4 + 255) / 256, 256>>>(w1, w1h, w1l, EW);
    split_kernel<<<(EW / 4 + 255) / 256, 256>>>(w3, w3h, w3l, EW);
    split_kernel<<<(EW / 4 + 255) / 256, 256>>>(w2, w2h, w2l, EW);
    split_kernel<<<(SW / 4 + 255) / 256, 256>>>(sw1, w1h + EW, w1l + EW, SW);
    split_kernel<<<(SW / 4 + 255) / 256, 256>>>(sw3, w3h + EW, w3l + EW, SW);
    split_kernel<<<(SW / 4 + 255) / 256, 256>>>(sw2, w2h + EW, w2l + EW, SW);

    router_kernel<<<N_TOK, 128>>>(x, wr);
    reduce_kernel<<<NEXP + 1, 256>>>();
    plan_kernel<<<1, 32>>>();
    scatter_kernel<<<(N_TOK + 255) / 256, 256>>>();

    stage1_kernel<<<dim3(MAX_MBLOCKS, HID / BN), 256, S1_TOTAL>>>();
    stage2_kernel<<<dim3(MAX_MBLOCKS, DMODEL / BN), 256, S2_TOTAL>>>();
    combine_kernel<<<N_TOK, 256>>>(out);
    finalize_kernel<<<1, 32>>>(out);
}

// round 7
// speedup vs baseline: 2.5913x; 1.1189x over previous
#include <cuda_runtime.h>
#include <cuda_bf16.h>
#include <math.h>
#include <stdint.h>

// ---------------- problem constants ----------------
#define N_TOK   4096
#define DMODEL  1024
#define NEXP    8
#define HID     1024
#define TOPK    2

// GEMM tiling (mma.sync bf16 path)
#define BM 128
#define BN 64
#define BK 32
#define APAD 8
#define BPAD 8
#define ASTR (BK + APAD)
#define BSTR (BN + BPAD)

#define MAX_MBLOCKS 104
#define MAX_ROWS    (MAX_MBLOCKS * BM)   // 13312

// dynamic smem layouts (3-stage pipelines)
#define S1_AH_B   (BM * ASTR * 2)                 // 10240
#define S1_B_B    (4 * BK * BSTR * 2)             // 18432
#define S1_STAGE  (2 * S1_AH_B + S1_B_B)          // 38912
#define S1_TOTAL  (512 + 3 * S1_STAGE)            // 117248

#define S2_B_B    (2 * BK * BSTR * 2)             // 9216
#define S2_STAGE  (2 * S1_AH_B + S2_B_B)          // 29696
#define S2_TOTAL  (3 * S2_STAGE)                  // 89088

// ---------------- device scratch ----------------
__device__ int   g_counts[NEXP];
__device__ int   g_fill[NEXP];
__device__ float g_probs[N_TOK * NEXP];
__device__ float g_lse2[N_TOK];
__device__ float g_probs_sum[NEXP];
__device__ float g_zsum;
__device__ int   g_expert_idx[N_TOK * TOPK];
__device__ float g_gate_w[N_TOK * TOPK];
__device__ int   g_row_tok[MAX_ROWS];
__device__ float g_row_w[MAX_ROWS];
__device__ int   g_row_pos[N_TOK * TOPK];
__device__ int   g_seg_start[NEXP + 1];
__device__ int   g_mb_expert[MAX_MBLOCKS];
__device__ int   g_n_mblocks;

__device__ __nv_bfloat16 g_x_hi[(size_t)N_TOK * DMODEL];
__device__ __nv_bfloat16 g_x_lo[(size_t)N_TOK * DMODEL];
__device__ __nv_bfloat16 g_w1_hi[(size_t)(NEXP + 1) * DMODEL * HID];
__device__ __nv_bfloat16 g_w1_lo[(size_t)(NEXP + 1) * DMODEL * HID];
__device__ __nv_bfloat16 g_w3_hi[(size_t)(NEXP + 1) * DMODEL * HID];
__device__ __nv_bfloat16 g_w3_lo[(size_t)(NEXP + 1) * DMODEL * HID];
__device__ __nv_bfloat16 g_w2_hi[(size_t)(NEXP + 1) * HID * DMODEL];
__device__ __nv_bfloat16 g_w2_lo[(size_t)(NEXP + 1) * HID * DMODEL];
__device__ __nv_bfloat16 g_h_hi[(size_t)MAX_ROWS * HID];
__device__ __nv_bfloat16 g_h_lo[(size_t)MAX_ROWS * HID];
__device__ float         g_ro[(size_t)MAX_ROWS * DMODEL];

// ---------------- asm helpers ----------------
__device__ __forceinline__ uint32_t smaddr(const void* p) {
    return (uint32_t)__cvta_generic_to_shared(p);
}
__device__ __forceinline__ void cpa16(uint32_t dst, const void* src, int szbytes) {
    asm volatile("cp.async.cg.shared.global [%0],[%1],16,%2;"
                 :: "r"(dst), "l"(src), "r"(szbytes));
}
__device__ __forceinline__ void cpa_commit() { asm volatile("cp.async.commit_group;"); }
template <int N>
__device__ __forceinline__ void cpa_wait() { asm volatile("cp.async.wait_group %0;" :: "n"(N)); }
__device__ __forceinline__ void ldsm4(uint32_t& r0, uint32_t& r1, uint32_t& r2, uint32_t& r3, uint32_t a) {
    asm volatile("ldmatrix.sync.aligned.m8n8.x4.shared.b16 {%0,%1,%2,%3},[%4];"
                 : "=r"(r0), "=r"(r1), "=r"(r2), "=r"(r3) : "r"(a));
}
__device__ __forceinline__ void ldsm4t(uint32_t& r0, uint32_t& r1, uint32_t& r2, uint32_t& r3, uint32_t a) {
    asm volatile("ldmatrix.sync.aligned.m8n8.x4.trans.shared.b16 {%0,%1,%2,%3},[%4];"
                 : "=r"(r0), "=r"(r1), "=r"(r2), "=r"(r3) : "r"(a));
}
__device__ __forceinline__ void mma16816(float* c, const uint32_t* a, uint32_t b0, uint32_t b1) {
    asm volatile("mma.sync.aligned.m16n8k16.row.col.f32.bf16.bf16.f32 "
                 "{%0,%1,%2,%3},{%4,%5,%6,%7},{%8,%9},{%0,%1,%2,%3};"
                 : "+f"(c[0]), "+f"(c[1]), "+f"(c[2]), "+f"(c[3])
                 : "r"(a[0]), "r"(a[1]), "r"(a[2]), "r"(a[3]), "r"(b0), "r"(b1));
}

// ---------------- init ----------------
__global__ void init_kernel() {
    int i = blockIdx.x * blockDim.x + threadIdx.x;
    if (i < MAX_ROWS) g_row_tok[i] = -1;
    if (i < NEXP) { g_counts[i] = 0; g_fill[i] = 0; }
    if (i == 0) g_zsum = 0.0f;
}

// ---------------- fp32 -> bf16 hi/lo split ----------------
__global__ __launch_bounds__(256) void split_kernel(const float* __restrict__ in,
                                                    __nv_bfloat16* __restrict__ hi,
                                                    __nv_bfloat16* __restrict__ lo, int n) {
    int i = (blockIdx.x * blockDim.x + threadIdx.x) * 4;
    if (i >= n) return;
    float4 v = *(const float4*)(in + i);
    __nv_bfloat16 h0 = __float2bfloat16(v.x);
    __nv_bfloat16 h1 = __float2bfloat16(v.y);
    __nv_bfloat16 h2 = __float2bfloat16(v.z);
    __nv_bfloat16 h3 = __float2bfloat16(v.w);
    *(__nv_bfloat162*)(hi + i)     = __nv_bfloat162(h0, h1);
    *(__nv_bfloat162*)(hi + i + 2) = __nv_bfloat162(h2, h3);
    *(__nv_bfloat162*)(lo + i)     = __nv_bfloat162(__float2bfloat16(v.x - __bfloat162float(h0)),
                                                    __float2bfloat16(v.y - __bfloat162float(h1)));
    *(__nv_bfloat162*)(lo + i + 2) = __nv_bfloat162(__float2bfloat16(v.z - __bfloat162float(h2)),
                                                    __float2bfloat16(v.w - __bfloat162float(h3)));
}

// ---------------- router ----------------
__global__ __launch_bounds__(128) void router_kernel(const float* __restrict__ x,
                                                     const float* __restrict__ wr) {
    int tok = blockIdx.x;
    int tid = threadIdx.x;
    const float* xr = x + (size_t)tok * DMODEL;

    float acc[NEXP];
#pragma unroll
    for (int e = 0; e < NEXP; e++) acc[e] = 0.0f;
    for (int d = tid; d < DMODEL; d += 128) {
        float xv = xr[d];
        const float4* w4 = (const float4*)(wr + (size_t)d * NEXP);
        float4 w0 = w4[0];
        float4 w1 = w4[1];
        acc[0] += xv * w0.x; acc[1] += xv * w0.y;
        acc[2] += xv * w0.z; acc[3] += xv * w0.w;
        acc[4] += xv * w1.x; acc[5] += xv * w1.y;
        acc[6] += xv * w1.z; acc[7] += xv * w1.w;
    }
#pragma unroll
    for (int off = 16; off > 0; off >>= 1)
#pragma unroll
        for (int e = 0; e < NEXP; e++)
            acc[e] += __shfl_down_sync(0xffffffffu, acc[e], off);

    __shared__ float s[4][NEXP];
    int w = tid >> 5, l = tid & 31;
    if (l == 0)
#pragma unroll
        for (int e = 0; e < NEXP; e++) s[w][e] = acc[e];
    __syncthreads();

    if (tid == 0) {
        float lg[NEXP];
#pragma unroll
        for (int e = 0; e < NEXP; e++)
            lg[e] = s[0][e] + s[1][e] + s[2][e] + s[3][e];
        float mx = lg[0];
#pragma unroll
        for (int e = 1; e < NEXP; e++) mx = fmaxf(mx, lg[e]);
        float p[NEXP], se = 0.0f;
#pragma unroll
        for (int e = 0; e < NEXP; e++) { p[e] = expf(lg[e] - mx); se += p[e]; }
        float inv = 1.0f / se;
#pragma unroll
        for (int e = 0; e < NEXP; e++) p[e] *= inv;
        float lse = mx + logf(se);

        int b0 = 0;
#pragma unroll
        for (int e = 1; e < NEXP; e++) if (lg[e] > lg[b0]) b0 = e;
        int b1 = (b0 == 0) ? 1 : 0;
#pragma unroll
        for (int e = 0; e < NEXP; e++)
            if (e != b0 && lg[e] > lg[b1]) b1 = e;

        g_expert_idx[tok * 2 + 0] = b0;
        g_expert_idx[tok * 2 + 1] = b1;
        g_gate_w[tok * 2 + 0] = p[b0];
        g_gate_w[tok * 2 + 1] = p[b1];
        atomicAdd(&g_counts[b0], 1);
        atomicAdd(&g_counts[b1], 1);
#pragma unroll
        for (int e = 0; e < NEXP; e++) g_probs[(size_t)tok * NEXP + e] = p[e];
        g_lse2[tok] = lse * lse;
    }
}

// ---------------- deterministic loss reductions ----------------
__global__ __launch_bounds__(256) void reduce_kernel() {
    int which = blockIdx.x;
    int tid = threadIdx.x;
    float s = 0.0f;
    if (which < NEXP) {
        for (int i = tid; i < N_TOK; i += 256) s += g_probs[(size_t)i * NEXP + which];
    } else {
        for (int i = tid; i < N_TOK; i += 256) s += g_lse2[i];
    }
#pragma unroll
    for (int off = 16; off > 0; off >>= 1)
        s += __shfl_down_sync(0xffffffffu, s, off);
    __shared__ float sm[8];
    if ((tid & 31) == 0) sm[tid >> 5] = s;
    __syncthreads();
    if (tid == 0) {
        float t = 0.0f;
#pragma unroll
        for (int i = 0; i < 8; i++) t += sm[i];
        if (which < NEXP) g_probs_sum[which] = t;
        else g_zsum = t;
    }
}

// ---------------- plan ----------------
__global__ void plan_kernel() {
    if (threadIdx.x == 0 && blockIdx.x == 0) {
        int acc = 0;
        for (int e = 0; e <= NEXP; e++) {
            int c = (e < NEXP) ? g_counts[e] : N_TOK;
            g_seg_start[e] = acc;
            int nmb = (c + BM - 1) / BM;
            int b0 = acc / BM;
            for (int i = 0; i < nmb; i++) g_mb_expert[b0 + i] = e;
            acc += nmb * BM;
        }
        g_n_mblocks = acc / BM;
    }
}

// ---------------- scatter ----------------
__global__ void scatter_kernel() {
    int tok = blockIdx.x * blockDim.x + threadIdx.x;
    if (tok >= N_TOK) return;
#pragma unroll
    for (int k = 0; k < TOPK; k++) {
        int e = g_expert_idx[tok * 2 + k];
        int p = g_seg_start[e] + atomicAdd(&g_fill[e], 1);
        g_row_tok[p] = tok;
        g_row_w[p] = g_gate_w[tok * 2 + k] * ((float)TOPK / (float)(TOPK + 1));
        g_row_pos[tok * 2 + k] = p;
    }
    int ps = g_seg_start[NEXP] + tok;
    g_row_tok[ps] = tok;
    g_row_w[ps] = 1.0f / (float)(TOPK + 1);
}

// ---------------- stage 1: h = silu(X@W1) * (X@W3)  [bf16x3 mma, 3-stage cp.async] ----------------
__global__ __launch_bounds__(256, 1) void stage1_kernel() {
    int mb = blockIdx.x;
    if (mb >= g_n_mblocks) return;
    int e = g_mb_expert[mb];
    const __nv_bfloat16* W1h = g_w1_hi + (size_t)e * DMODEL * HID;
    const __nv_bfloat16* W1l = g_w1_lo + (size_t)e * DMODEL * HID;
    const __nv_bfloat16* W3h = g_w3_hi + (size_t)e * DMODEL * HID;
    const __nv_bfloat16* W3l = g_w3_lo + (size_t)e * DMODEL * HID;
    int row0 = mb * BM;
    int n0 = blockIdx.y * BN;

    extern __shared__ char dsm[];
    int* toks = (int*)dsm;
    char* base = dsm + 512;

    int tid = threadIdx.x, lane = tid & 31, warp = tid >> 5;
    if (tid < BM) toks[tid] = g_row_tok[row0 + tid];
    __syncthreads();

    int wm = warp >> 1, wn = warp & 1;

    float accg[2][4][4], accu[2][4][4];
#pragma unroll
    for (int mi = 0; mi < 2; mi++)
#pragma unroll
        for (int ni = 0; ni < 4; ni++)
#pragma unroll
            for (int q = 0; q < 4; q++) { accg[mi][ni][q] = 0.0f; accu[mi][ni][q] = 0.0f; }

    int ar = tid >> 2, ac = (tid & 3) * 8;
    int br = tid >> 3, bc = (tid & 7) * 8;
    int tok0 = toks[ar];
    int tok1 = toks[64 + ar];
    int sz0 = (tok0 >= 0) ? 16 : 0;
    int sz1 = (tok1 >= 0) ? 16 : 0;
    size_t xb0 = (tok0 >= 0) ? ((size_t)tok0 * DMODEL + ac) : 0;
    size_t xb1 = (tok1 >= 0) ? ((size_t)tok1 * DMODEL + ac) : 0;

    const int NIT = DMODEL / BK;

    auto issue = [&](int it, int buf) {
        char* st = base + buf * S1_STAGE;
        __nv_bfloat16* sAh = (__nv_bfloat16*)st;
        __nv_bfloat16* sAl = sAh + BM * ASTR;
        __nv_bfloat16* sB  = sAl + BM * ASTR;
        int kk = it * BK;
        cpa16(smaddr(&sAh[ar * ASTR + ac]),        &g_x_hi[xb0 + kk], sz0);
        cpa16(smaddr(&sAl[ar * ASTR + ac]),        &g_x_lo[xb0 + kk], sz0);
        cpa16(smaddr(&sAh[(64 + ar) * ASTR + ac]), &g_x_hi[xb1 + kk], sz1);
        cpa16(smaddr(&sAl[(64 + ar) * ASTR + ac]), &g_x_lo[xb1 + kk], sz1);
        size_t bo = (size_t)(kk + br) * HID + n0 + bc;
        cpa16(smaddr(&sB[(0 * BK + br) * BSTR + bc]), &W1h[bo], 16);
        cpa16(smaddr(&sB[(1 * BK + br) * BSTR + bc]), &W1l[bo], 16);
        cpa16(smaddr(&sB[(2 * BK + br) * BSTR + bc]), &W3h[bo], 16);
        cpa16(smaddr(&sB[(3 * BK + br) * BSTR + bc]), &W3l[bo], 16);
        cpa_commit();
    };

    issue(0, 0);
    issue(1, 1);

    for (int it = 0; it < NIT; it++) {
        int buf = it % 3;
        cpa_wait<1>();
        __syncthreads();

        char* st = base + buf * S1_STAGE;
        __nv_bfloat16* sAh = (__nv_bfloat16*)st;
        __nv_bfloat16* sAl = sAh + BM * ASTR;
        __nv_bfloat16* sB  = sAl + BM * ASTR;

#pragma unroll
        for (int ks = 0; ks < 2; ks++) {
            int k0 = ks * 16;
            uint32_t ah[2][4], al[2][4];
#pragma unroll
            for (int mi = 0; mi < 2; mi++) {
                int arow = wm * 32 + mi * 16 + (lane & 15);
                int acol = k0 + (lane >> 4) * 8;
                ldsm4(ah[mi][0], ah[mi][1], ah[mi][2], ah[mi][3], smaddr(&sAh[arow * ASTR + acol]));
                ldsm4(al[mi][0], al[mi][1], al[mi][2], al[mi][3], smaddr(&sAl[arow * ASTR + acol]));
            }
            uint32_t bf[4][8];
#pragma unroll
            for (int v = 0; v < 4; v++)
#pragma unroll
                for (int hh = 0; hh < 2; hh++) {
                    int brow = k0 + (lane & 15);
                    int bcol = wn * 32 + hh * 16 + (lane >> 4) * 8;
                    ldsm4t(bf[v][hh * 4 + 0], bf[v][hh * 4 + 1], bf[v][hh * 4 + 2], bf[v][hh * 4 + 3],
                           smaddr(&sB[(v * BK + brow) * BSTR + bcol]));
                }
#pragma unroll
            for (int mi = 0; mi < 2; mi++)
#pragma unroll
                for (int ni = 0; ni < 4; ni++) {
                    int rb = (ni >> 1) * 4 + (ni & 1) * 2;
                    mma16816(accg[mi][ni], ah[mi], bf[0][rb], bf[0][rb + 1]);
                    mma16816(accg[mi][ni], ah[mi], bf[1][rb], bf[1][rb + 1]);
                    mma16816(accg[mi][ni], al[mi], bf[0][rb], bf[0][rb + 1]);
                    mma16816(accu[mi][ni], ah[mi], bf[2][rb], bf[2][rb + 1]);
                    mma16816(accu[mi][ni], ah[mi], bf[3][rb], bf[3][rb + 1]);
                    mma16816(accu[mi][ni], al[mi], bf[2][rb], bf[2][rb + 1]);
                }
        }

        if (it + 2 < NIT) issue(it + 2, (it + 2) % 3);
        else cpa_commit();   // keep group count uniform
    }

    // epilogue: SwiGLU + split to bf16 hi/lo
#pragma unroll
    for (int mi = 0; mi < 2; mi++)
#pragma unroll
        for (int ni = 0; ni < 4; ni++) {
            int r = row0 + wm * 32 + mi * 16 + (lane >> 2);
            int c = n0 + wn * 32 + ni * 8 + (lane & 3) * 2;
#pragma unroll
            for (int pr = 0; pr < 2; pr++) {
                int rr = r + pr * 8;
                float g0 = accg[mi][ni][pr * 2 + 0];
                float g1 = accg[mi][ni][pr * 2 + 1];
                float u0 = accu[mi][ni][pr * 2 + 0];
                float u1 = accu[mi][ni][pr * 2 + 1];
                float h0 = g0 / (1.0f + expf(-g0)) * u0;
                float h1 = g1 / (1.0f + expf(-g1)) * u1;
                __nv_bfloat16 h0h = __float2bfloat16(h0);
                __nv_bfloat16 h1h = __float2bfloat16(h1);
                __nv_bfloat16 h0l = __float2bfloat16(h0 - __bfloat162float(h0h));
                __nv_bfloat16 h1l = __float2bfloat16(h1 - __bfloat162float(h1h));
                *(__nv_bfloat162*)&g_h_hi[(size_t)rr * HID + c] = __nv_bfloat162(h0h, h1h);
                *(__nv_bfloat162*)&g_h_lo[(size_t)rr * HID + c] = __nv_bfloat162(h0l, h1l);
            }
        }
}

// ---------------- stage 2: ro = h @ W2  [bf16x3 mma, 3-stage cp.async, 2 CTAs/SM] ----------------
__global__ __launch_bounds__(256, 2) void stage2_kernel() {
    int mb = blockIdx.x;
    if (mb >= g_n_mblocks) return;
    int e = g_mb_expert[mb];
    const __nv_bfloat16* W2h = g_w2_hi + (size_t)e * HID * DMODEL;
    const __nv_bfloat16* W2l = g_w2_lo + (size_t)e * HID * DMODEL;
    int row0 = mb * BM;
    int n0 = blockIdx.y * BN;

    extern __shared__ char dsm[];
    char* base = dsm;

    int tid = threadIdx.x, lane = tid & 31, warp = tid >> 5;
    int wm = warp >> 1, wn = warp & 1;

    float acc[2][4][4];
#pragma unroll
    for (int mi = 0; mi < 2; mi++)
#pragma unroll
        for (int ni = 0; ni < 4; ni++)
#pragma unroll
            for (int q = 0; q < 4; q++) acc[mi][ni][q] = 0.0f;

    int ar = tid >> 2, ac = (tid & 3) * 8;
    int br = tid >> 3, bc = (tid & 7) * 8;

    const int NIT = HID / BK;

    auto issue = [&](int it, int buf) {
        char* st = base + buf * S2_STAGE;
        __nv_bfloat16* sAh = (__nv_bfloat16*)st;
        __nv_bfloat16* sAl = sAh + BM * ASTR;
        __nv_bfloat16* sB  = sAl + BM * ASTR;
        int kk = it * BK;
#pragma unroll
        for (int hh = 0; hh < 2; hh++) {
            int r = hh * 64 + ar;
            size_t ao = (size_t)(row0 + r) * HID + kk + ac;
            cpa16(smaddr(&sAh[r * ASTR + ac]), &g_h_hi[ao], 16);
            cpa16(smaddr(&sAl[r * ASTR + ac]), &g_h_lo[ao], 16);
        }
        size_t bo = (size_t)(kk + br) * DMODEL + n0 + bc;
        cpa16(smaddr(&sB[(0 * BK + br) * BSTR + bc]), &W2h[bo], 16);
        cpa16(smaddr(&sB[(1 * BK + br) * BSTR + bc]), &W2l[bo], 16);
        cpa_commit();
    };

    issue(0, 0);
    issue(1, 1);

    for (int it = 0; it < NIT; it++) {
        int buf = it % 3;
        cpa_wait<1>();
        __syncthreads();

        char* st = base + buf * S2_STAGE;
        __nv_bfloat16* sAh = (__nv_bfloat16*)st;
        __nv_bfloat16* sAl = sAh + BM * ASTR;
        __nv_bfloat16* sB  = sAl + BM * ASTR;

#pragma unroll
        for (int ks = 0; ks < 2; ks++) {
            int k0 = ks * 16;
            uint32_t ah[2][4], al[2][4];
#pragma unroll
            for (int mi = 0; mi < 2; mi++) {
                int arow = wm * 32 + mi * 16 + (lane & 15);
                int acol = k0 + (lane >> 4) * 8;
                ldsm4(ah[mi][0], ah[mi][1], ah[mi][2], ah[mi][3], smaddr(&sAh[arow * ASTR + acol]));
                ldsm4(al[mi][0], al[mi][1], al[mi][2], al[mi][3], smaddr(&sAl[arow * ASTR + acol]));
            }
            uint32_t bf[2][8];
#pragma unroll
            for (int v = 0; v < 2; v++)
#pragma unroll
                for (int hh = 0; hh < 2; hh++) {
                    int brow = k0 + (lane & 15);
                    int bcol = wn * 32 + hh * 16 + (lane >> 4) * 8;
                    ldsm4t(bf[v][hh * 4 + 0], bf[v][hh * 4 + 1], bf[v][hh * 4 + 2], bf[v][hh * 4 + 3],
                           smaddr(&sB[(v * BK + brow) * BSTR + bcol]));
                }
#pragma unroll
            for (int mi = 0; mi < 2; mi++)
#pragma unroll
                for (int ni = 0; ni < 4; ni++) {
                    int rb = (ni >> 1) * 4 + (ni & 1) * 2;
                    mma16816(acc[mi][ni], ah[mi], bf[0][rb], bf[0][rb + 1]);
                    mma16816(acc[mi][ni], ah[mi], bf[1][rb], bf[1][rb + 1]);
                    mma16816(acc[mi][ni], al[mi], bf[0][rb], bf[0][rb + 1]);
                }
        }

        if (it + 2 < NIT) issue(it + 2, (it + 2) % 3);
        else cpa_commit();
    }

#pragma unroll
    for (int mi = 0; mi < 2; mi++)
#pragma unroll
        for (int ni = 0; ni < 4; ni++) {
            int r = row0 + wm * 32 + mi * 16 + (lane >> 2);
            int c = n0 + wn * 32 + ni * 8 + (lane & 3) * 2;
#pragma unroll
            for (int pr = 0; pr < 2; pr++) {
                int rr = r + pr * 8;
                float2 o = make_float2(acc[mi][ni][pr * 2 + 0], acc[mi][ni][pr * 2 + 1]);
                *(float2*)&g_ro[(size_t)rr * DMODEL + c] = o;
            }
        }
}

// ---------------- deterministic weighted combine ----------------
__global__ __launch_bounds__(256) void combine_kernel(float* __restrict__ out) {
    int tok = blockIdx.x;
    int p0 = g_row_pos[tok * 2 + 0];
    int p1 = g_row_pos[tok * 2 + 1];
    int ps = g_seg_start[NEXP] + tok;
    float w0 = g_row_w[p0];
    float w1 = g_row_w[p1];
    const float ws = 1.0f / (float)(TOPK + 1);
    for (int d = threadIdx.x; d < DMODEL; d += 256) {
        float v = w0 * g_ro[(size_t)p0 * DMODEL + d]
                + w1 * g_ro[(size_t)p1 * DMODEL + d]
                + ws * g_ro[(size_t)ps * DMODEL + d];
        out[(size_t)tok * DMODEL + d] = v;
    }
}

// ---------------- losses ----------------
__global__ void finalize_kernel(float* __restrict__ out) {
    if (threadIdx.x == 0 && blockIdx.x == 0) {
        float lb = 0.0f;
        for (int e = 0; e < NEXP; e++)
            lb += (float)g_counts[e] * g_probs_sum[e];
        lb *= (float)NEXP * 0.01f / (16.0f * (float)N_TOK * (float)TOPK);
        out[(size_t)N_TOK * DMODEL + 0] = lb;
        out[(size_t)N_TOK * DMODEL + 1] = 0.001f * g_zsum / (float)N_TOK;
    }
}

// ---------------- launch ----------------
extern "C" void kernel_launch(void* const* d_in, const int* in_sizes, int n_in,
                              void* d_out, int out_size) {
    const float* x   = (const float*)d_in[0];
    const float* wr  = (const float*)d_in[1];
    const float* w1  = (const float*)d_in[2];
    const float* w3  = (const float*)d_in[3];
    const float* w2  = (const float*)d_in[4];
    const float* sw1 = (const float*)d_in[5];
    const float* sw3 = (const float*)d_in[6];
    const float* sw2 = (const float*)d_in[7];
    float* out = (float*)d_out;

    static int s_attr_done = 0;
    if (!s_attr_done) {
        cudaFuncSetAttribute(stage1_kernel, cudaFuncAttributeMaxDynamicSharedMemorySize, S1_TOTAL);
        cudaFuncSetAttribute(stage2_kernel, cudaFuncAttributeMaxDynamicSharedMemorySize, S2_TOTAL);
        s_attr_done = 1;
    }

    __nv_bfloat16 *xh, *xl, *w1h, *w1l, *w3h, *w3l, *w2h, *w2l;
    cudaGetSymbolAddress((void**)&xh,  g_x_hi);
    cudaGetSymbolAddress((void**)&xl,  g_x_lo);
    cudaGetSymbolAddress((void**)&w1h, g_w1_hi);
    cudaGetSymbolAddress((void**)&w1l, g_w1_lo);
    cudaGetSymbolAddress((void**)&w3h, g_w3_hi);
    cudaGetSymbolAddress((void**)&w3l, g_w3_lo);
    cudaGetSymbolAddress((void**)&w2h, g_w2_hi);
    cudaGetSymbolAddress((void**)&w2l, g_w2_lo);

    const int EW = NEXP * DMODEL * HID;
    const int SW = DMODEL * HID;
    const int NX = N_TOK * DMODEL;

    init_kernel<<<(MAX_ROWS + 255) / 256, 256>>>();
    split_kernel<<<(NX / 4 + 255) / 256, 256>>>(x, xh, xl, NX);
    split_kernel<<<(EW / 4 + 255) / 256, 256>>>(w1, w1h, w1l, EW);
    split_kernel<<<(EW / 4 + 255) / 256, 256>>>(w3, w3h, w3l, EW);
    split_kernel<<<(EW / 4 + 255) / 256, 256>>>(w2, w2h, w2l, EW);
    split_kernel<<<(SW / 4 + 255) / 256, 256>>>(sw1, w1h + EW, w1l + EW, SW);
    split_kernel<<<(SW / 4 + 255) / 256, 256>>>(sw3, w3h + EW, w3l + EW, SW);
    split_kernel<<<(SW / 4 + 255) / 256, 256>>>(sw2, w2h + EW, w2l + EW, SW);

    router_kernel<<<N_TOK, 128>>>(x, wr);
    reduce_kernel<<<NEXP + 1, 256>>>();
    plan_kernel<<<1, 32>>>();
    scatter_kernel<<<(N_TOK + 255) / 256, 256>>>();

    stage1_kernel<<<dim3(MAX_MBLOCKS, HID / BN), 256, S1_TOTAL>>>();
    stage2_kernel<<<dim3(MAX_MBLOCKS, DMODEL / BN), 256, S2_TOTAL>>>();
    combine_kernel<<<N_TOK, 256>>>(out);
    finalize_kernel<<<1, 32>>>(out);
}

// round 11
// speedup vs baseline: 2.7338x; 1.0550x over previous
#include <cuda_runtime.h>
#include <cuda_bf16.h>
#include <math.h>
#include <stdint.h>

// ---------------- problem constants ----------------
#define N_TOK   4096
#define DMODEL  1024
#define NEXP    8
#define HID     1024
#define TOPK    2

// GEMM tiling (mma.sync bf16 path)
#define BM 128
#define BN 64
#define BK 32
#define APAD 8
#define BPAD 8
#define ASTR (BK + APAD)
#define BSTR (BN + BPAD)

#define MAX_MBLOCKS 104
#define MAX_ROWS    (MAX_MBLOCKS * BM)   // 13312

// dynamic smem layouts
#define S1_AH_B   (BM * ASTR * 2)                 // 10240
#define S1_B_B    (4 * BK * BSTR * 2)             // 18432
#define S1_STAGE  (2 * S1_AH_B + S1_B_B)          // 38912
#define S1_TOTAL  (512 + 2 * S1_STAGE)            // 78336  (2-stage -> 2 CTAs/SM)

#define S2_B_B    (2 * BK * BSTR * 2)             // 9216
#define S2_STAGE  (2 * S1_AH_B + S2_B_B)          // 29696
#define S2_TOTAL  (3 * S2_STAGE)                  // 89088  (3-stage, 2 CTAs/SM)

// ---------------- device scratch ----------------
__device__ int   g_counts[NEXP];
__device__ float g_probs[N_TOK * NEXP];
__device__ float g_lse2[N_TOK];
__device__ float g_probs_sum[NEXP];
__device__ float g_zsum;
__device__ int   g_expert_idx[N_TOK * TOPK];
__device__ float g_gate_w[N_TOK * TOPK];
__device__ int   g_row_tok[MAX_ROWS];
__device__ float g_row_w[MAX_ROWS];
__device__ int   g_row_pos[N_TOK * TOPK];
__device__ int   g_seg_start[NEXP + 1];
__device__ int   g_mb_expert[MAX_MBLOCKS];
__device__ int   g_n_mblocks;

__device__ __nv_bfloat16 g_x_hi[(size_t)N_TOK * DMODEL];
__device__ __nv_bfloat16 g_x_lo[(size_t)N_TOK * DMODEL];
__device__ __nv_bfloat16 g_w1_hi[(size_t)(NEXP + 1) * DMODEL * HID];
__device__ __nv_bfloat16 g_w1_lo[(size_t)(NEXP + 1) * DMODEL * HID];
__device__ __nv_bfloat16 g_w3_hi[(size_t)(NEXP + 1) * DMODEL * HID];
__device__ __nv_bfloat16 g_w3_lo[(size_t)(NEXP + 1) * DMODEL * HID];
__device__ __nv_bfloat16 g_w2_hi[(size_t)(NEXP + 1) * HID * DMODEL];
__device__ __nv_bfloat16 g_w2_lo[(size_t)(NEXP + 1) * HID * DMODEL];
__device__ __nv_bfloat16 g_h_hi[(size_t)MAX_ROWS * HID];
__device__ __nv_bfloat16 g_h_lo[(size_t)MAX_ROWS * HID];
__device__ float         g_ro[(size_t)MAX_ROWS * DMODEL];

// ---------------- asm helpers ----------------
__device__ __forceinline__ uint32_t smaddr(const void* p) {
    return (uint32_t)__cvta_generic_to_shared(p);
}
__device__ __forceinline__ void cpa16(uint32_t dst, const void* src, int szbytes) {
    asm volatile("cp.async.cg.shared.global [%0],[%1],16,%2;"
                 :: "r"(dst), "l"(src), "r"(szbytes));
}
__device__ __forceinline__ void cpa_commit() { asm volatile("cp.async.commit_group;"); }
template <int N>
__device__ __forceinline__ void cpa_wait() { asm volatile("cp.async.wait_group %0;" :: "n"(N)); }
__device__ __forceinline__ void ldsm4(uint32_t& r0, uint32_t& r1, uint32_t& r2, uint32_t& r3, uint32_t a) {
    asm volatile("ldmatrix.sync.aligned.m8n8.x4.shared.b16 {%0,%1,%2,%3},[%4];"
                 : "=r"(r0), "=r"(r1), "=r"(r2), "=r"(r3) : "r"(a));
}
__device__ __forceinline__ void ldsm4t(uint32_t& r0, uint32_t& r1, uint32_t& r2, uint32_t& r3, uint32_t a) {
    asm volatile("ldmatrix.sync.aligned.m8n8.x4.trans.shared.b16 {%0,%1,%2,%3},[%4];"
                 : "=r"(r0), "=r"(r1), "=r"(r2), "=r"(r3) : "r"(a));
}
__device__ __forceinline__ void mma16816(float* c, const uint32_t* a, uint32_t b0, uint32_t b1) {
    asm volatile("mma.sync.aligned.m16n8k16.row.col.f32.bf16.bf16.f32 "
                 "{%0,%1,%2,%3},{%4,%5,%6,%7},{%8,%9},{%0,%1,%2,%3};"
                 : "+f"(c[0]), "+f"(c[1]), "+f"(c[2]), "+f"(c[3])
                 : "r"(a[0]), "r"(a[1]), "r"(a[2]), "r"(a[3]), "r"(b0), "r"(b1));
}
__device__ __forceinline__ uint32_t pack_bf2(float a, float b) {
    __nv_bfloat162 v(__float2bfloat16(a), __float2bfloat16(b));
    return *(uint32_t*)&v;
}

// ---------------- split 8 fp32 -> 16B hi + 16B lo ----------------
__device__ __forceinline__ void split8(const float* __restrict__ src,
                                       __nv_bfloat16* __restrict__ hi,
                                       __nv_bfloat16* __restrict__ lo, size_t off) {
    float4 a = *(const float4*)(src + off);
    float4 b = *(const float4*)(src + off + 4);
    float f[8] = { a.x, a.y, a.z, a.w, b.x, b.y, b.z, b.w };
    uint32_t ph[4], pl[4];
#pragma unroll
    for (int i = 0; i < 4; i++) {
        __nv_bfloat16 h0 = __float2bfloat16(f[2 * i]);
        __nv_bfloat16 h1 = __float2bfloat16(f[2 * i + 1]);
        __nv_bfloat162 hv(h0, h1);
        ph[i] = *(uint32_t*)&hv;
        __nv_bfloat162 lv(__float2bfloat16(f[2 * i] - __bfloat162float(h0)),
                          __float2bfloat16(f[2 * i + 1] - __bfloat162float(h1)));
        pl[i] = *(uint32_t*)&lv;
    }
    *(uint4*)(hi + off) = make_uint4(ph[0], ph[1], ph[2], ph[3]);
    *(uint4*)(lo + off) = make_uint4(pl[0], pl[1], pl[2], pl[3]);
}

// ---------------- prep: x split + init ----------------
__global__ __launch_bounds__(256) void prep_kernel(const float* __restrict__ x) {
    int gid = blockIdx.x * blockDim.x + threadIdx.x;
    size_t off = (size_t)gid * 8;
    if (off < (size_t)N_TOK * DMODEL) split8(x, g_x_hi, g_x_lo, off);
    if (gid < MAX_ROWS) g_row_tok[gid] = -1;
    if (gid < NEXP) g_counts[gid] = 0;
    if (gid == 0) g_zsum = 0.0f;
}

// ---------------- all weight splits in one launch ----------------
// regions (in 1M-elem units): w1[0,8) sw1[8,9) w3[9,17) sw3[17,18) w2[18,26) sw2[26,27)
__global__ __launch_bounds__(256) void splitw_kernel(const float* __restrict__ w1,
                                                     const float* __restrict__ w3,
                                                     const float* __restrict__ w2,
                                                     const float* __restrict__ sw1,
                                                     const float* __restrict__ sw3,
                                                     const float* __restrict__ sw2) {
    const size_t M1 = (size_t)DMODEL * HID;      // 1M
    const size_t EW = (size_t)NEXP * M1;         // 8M
    size_t off = ((size_t)blockIdx.x * blockDim.x + threadIdx.x) * 8;
    if (off < EW)                 { split8(w1,  g_w1_hi,      g_w1_lo,      off); return; }
    off -= EW;
    if (off < M1)                 { split8(sw1, g_w1_hi + EW, g_w1_lo + EW, off); return; }
    off -= M1;
    if (off < EW)                 { split8(w3,  g_w3_hi,      g_w3_lo,      off); return; }
    off -= EW;
    if (off < M1)                 { split8(sw3, g_w3_hi + EW, g_w3_lo + EW, off); return; }
    off -= M1;
    if (off < EW)                 { split8(w2,  g_w2_hi,      g_w2_lo,      off); return; }
    off -= EW;
    if (off < M1)                 { split8(sw2, g_w2_hi + EW, g_w2_lo + EW, off); return; }
}

// ---------------- router ----------------
__global__ __launch_bounds__(128) void router_kernel(const float* __restrict__ x,
                                                     const float* __restrict__ wr) {
    int tok = blockIdx.x;
    int tid = threadIdx.x;
    const float* xr = x + (size_t)tok * DMODEL;

    float acc[NEXP];
#pragma unroll
    for (int e = 0; e < NEXP; e++) acc[e] = 0.0f;
    for (int d = tid; d < DMODEL; d += 128) {
        float xv = xr[d];
        const float4* w4 = (const float4*)(wr + (size_t)d * NEXP);
        float4 w0 = w4[0];
        float4 w1 = w4[1];
        acc[0] += xv * w0.x; acc[1] += xv * w0.y;
        acc[2] += xv * w0.z; acc[3] += xv * w0.w;
        acc[4] += xv * w1.x; acc[5] += xv * w1.y;
        acc[6] += xv * w1.z; acc[7] += xv * w1.w;
    }
#pragma unroll
    for (int off = 16; off > 0; off >>= 1)
#pragma unroll
        for (int e = 0; e < NEXP; e++)
            acc[e] += __shfl_down_sync(0xffffffffu, acc[e], off);

    __shared__ float s[4][NEXP];
    int w = tid >> 5, l = tid & 31;
    if (l == 0)
#pragma unroll
        for (int e = 0; e < NEXP; e++) s[w][e] = acc[e];
    __syncthreads();

    if (tid == 0) {
        float lg[NEXP];
#pragma unroll
        for (int e = 0; e < NEXP; e++)
            lg[e] = s[0][e] + s[1][e] + s[2][e] + s[3][e];
        float mx = lg[0];
#pragma unroll
        for (int e = 1; e < NEXP; e++) mx = fmaxf(mx, lg[e]);
        float p[NEXP], se = 0.0f;
#pragma unroll
        for (int e = 0; e < NEXP; e++) { p[e] = expf(lg[e] - mx); se += p[e]; }
        float inv = 1.0f / se;
#pragma unroll
        for (int e = 0; e < NEXP; e++) p[e] *= inv;
        float lse = mx + logf(se);

        int b0 = 0;
#pragma unroll
        for (int e = 1; e < NEXP; e++) if (lg[e] > lg[b0]) b0 = e;
        int b1 = (b0 == 0) ? 1 : 0;
#pragma unroll
        for (int e = 0; e < NEXP; e++)
            if (e != b0 && lg[e] > lg[b1]) b1 = e;

        g_expert_idx[tok * 2 + 0] = b0;
        g_expert_idx[tok * 2 + 1] = b1;
        g_gate_w[tok * 2 + 0] = p[b0];
        g_gate_w[tok * 2 + 1] = p[b1];
        atomicAdd(&g_counts[b0], 1);
        atomicAdd(&g_counts[b1], 1);
#pragma unroll
        for (int e = 0; e < NEXP; e++) g_probs[(size_t)tok * NEXP + e] = p[e];
        g_lse2[tok] = lse * lse;
    }
}

// ---------------- deterministic loss reductions ----------------
__global__ __launch_bounds__(256) void reduce_kernel() {
    int which = blockIdx.x;
    int tid = threadIdx.x;
    float s = 0.0f;
    if (which < NEXP) {
        for (int i = tid; i < N_TOK; i += 256) s += g_probs[(size_t)i * NEXP + which];
    } else {
        for (int i = tid; i < N_TOK; i += 256) s += g_lse2[i];
    }
#pragma unroll
    for (int off = 16; off > 0; off >>= 1)
        s += __shfl_down_sync(0xffffffffu, s, off);
    __shared__ float sm[8];
    if ((tid & 31) == 0) sm[tid >> 5] = s;
    __syncthreads();
    if (tid == 0) {
        float t = 0.0f;
#pragma unroll
        for (int i = 0; i < 8; i++) t += sm[i];
        if (which < NEXP) g_probs_sum[which] = t;
        else g_zsum = t;
    }
}

// ---------------- plan + scatter in ONE single-block kernel ----------------
__global__ __launch_bounds__(1024) void planscatter_kernel() {
    __shared__ int sfill[NEXP];
    int tid = threadIdx.x;
    if (tid == 0) {
        int acc = 0;
        for (int e = 0; e <= NEXP; e++) {
            int c = (e < NEXP) ? g_counts[e] : N_TOK;
            g_seg_start[e] = acc;
            int nmb = (c + BM - 1) / BM;
            int b0 = acc / BM;
            for (int i = 0; i < nmb; i++) g_mb_expert[b0 + i] = e;
            acc += nmb * BM;
        }
        g_n_mblocks = acc / BM;
    }
    if (tid < NEXP) sfill[tid] = 0;
    __syncthreads();
    for (int tok = tid; tok < N_TOK; tok += 1024) {
#pragma unroll
        for (int k = 0; k < TOPK; k++) {
            int e = g_expert_idx[tok * 2 + k];
            int p = g_seg_start[e] + atomicAdd(&sfill[e], 1);
            g_row_tok[p] = tok;
            g_row_w[p] = g_gate_w[tok * 2 + k] * ((float)TOPK / (float)(TOPK + 1));
            g_row_pos[tok * 2 + k] = p;
        }
        int ps = g_seg_start[NEXP] + tok;
        g_row_tok[ps] = tok;
        g_row_w[ps] = 1.0f / (float)(TOPK + 1);
    }
}

// ---------------- stage 1: h = silu(X@W1) * (X@W3)  [2-stage cp.async, 2 CTAs/SM] ----------------
__global__ __launch_bounds__(256, 2) void stage1_kernel() {
    int mb = blockIdx.x;
    if (mb >= g_n_mblocks) return;
    int e = g_mb_expert[mb];
    const __nv_bfloat16* W1h = g_w1_hi + (size_t)e * DMODEL * HID;
    const __nv_bfloat16* W1l = g_w1_lo + (size_t)e * DMODEL * HID;
    const __nv_bfloat16* W3h = g_w3_hi + (size_t)e * DMODEL * HID;
    const __nv_bfloat16* W3l = g_w3_lo + (size_t)e * DMODEL * HID;
    int row0 = mb * BM;
    int n0 = blockIdx.y * BN;

    extern __shared__ char dsm[];
    int* toks = (int*)dsm;
    char* base = dsm + 512;

    int tid = threadIdx.x, lane = tid & 31, warp = tid >> 5;
    if (tid < BM) toks[tid] = g_row_tok[row0 + tid];
    __syncthreads();

    int wm = warp >> 1, wn = warp & 1;

    float accg[2][4][4], accu[2][4][4];
#pragma unroll
    for (int mi = 0; mi < 2; mi++)
#pragma unroll
        for (int ni = 0; ni < 4; ni++)
#pragma unroll
            for (int q = 0; q < 4; q++) { accg[mi][ni][q] = 0.0f; accu[mi][ni][q] = 0.0f; }

    int ar = tid >> 2, ac = (tid & 3) * 8;
    int br = tid >> 3, bc = (tid & 7) * 8;
    int tok0 = toks[ar];
    int tok1 = toks[64 + ar];
    int sz0 = (tok0 >= 0) ? 16 : 0;
    int sz1 = (tok1 >= 0) ? 16 : 0;
    size_t xb0 = (tok0 >= 0) ? ((size_t)tok0 * DMODEL + ac) : 0;
    size_t xb1 = (tok1 >= 0) ? ((size_t)tok1 * DMODEL + ac) : 0;

    const int NIT = DMODEL / BK;

    auto issue = [&](int it, int buf) {
        char* st = base + buf * S1_STAGE;
        __nv_bfloat16* sAh = (__nv_bfloat16*)st;
        __nv_bfloat16* sAl = sAh + BM * ASTR;
        __nv_bfloat16* sB  = sAl + BM * ASTR;
        int kk = it * BK;
        cpa16(smaddr(&sAh[ar * ASTR + ac]),        &g_x_hi[xb0 + kk], sz0);
        cpa16(smaddr(&sAl[ar * ASTR + ac]),        &g_x_lo[xb0 + kk], sz0);
        cpa16(smaddr(&sAh[(64 + ar) * ASTR + ac]), &g_x_hi[xb1 + kk], sz1);
        cpa16(smaddr(&sAl[(64 + ar) * ASTR + ac]), &g_x_lo[xb1 + kk], sz1);
        size_t bo = (size_t)(kk + br) * HID + n0 + bc;
        cpa16(smaddr(&sB[(0 * BK + br) * BSTR + bc]), &W1h[bo], 16);
        cpa16(smaddr(&sB[(1 * BK + br) * BSTR + bc]), &W1l[bo], 16);
        cpa16(smaddr(&sB[(2 * BK + br) * BSTR + bc]), &W3h[bo], 16);
        cpa16(smaddr(&sB[(3 * BK + br) * BSTR + bc]), &W3l[bo], 16);
        cpa_commit();
    };

    issue(0, 0);

    for (int it = 0; it < NIT; it++) {
        int buf = it & 1;
        cpa_wait<0>();
        __syncthreads();
        if (it + 1 < NIT) issue(it + 1, buf ^ 1);   // overlaps with compute below

        char* st = base + buf * S1_STAGE;
        __nv_bfloat16* sAh = (__nv_bfloat16*)st;
        __nv_bfloat16* sAl = sAh + BM * ASTR;
        __nv_bfloat16* sB  = sAl + BM * ASTR;

#pragma unroll
        for (int ks = 0; ks < 2; ks++) {
            int k0 = ks * 16;
            uint32_t ah[2][4], al[2][4];
#pragma unroll
            for (int mi = 0; mi < 2; mi++) {
                int arow = wm * 32 + mi * 16 + (lane & 15);
                int acol = k0 + (lane >> 4) * 8;
                ldsm4(ah[mi][0], ah[mi][1], ah[mi][2], ah[mi][3], smaddr(&sAh[arow * ASTR + acol]));
                ldsm4(al[mi][0], al[mi][1], al[mi][2], al[mi][3], smaddr(&sAl[arow * ASTR + acol]));
            }
            int brow = k0 + (lane & 15);
            int bcolb = wn * 32 + (lane >> 4) * 8;
            // W1 pair -> accg
            {
                uint32_t bh[8], bl[8];
#pragma unroll
                for (int hh = 0; hh < 2; hh++) {
                    int bcol = bcolb + hh * 16;
                    ldsm4t(bh[hh * 4 + 0], bh[hh * 4 + 1], bh[hh * 4 + 2], bh[hh * 4 + 3],
                           smaddr(&sB[(0 * BK + brow) * BSTR + bcol]));
                    ldsm4t(bl[hh * 4 + 0], bl[hh * 4 + 1], bl[hh * 4 + 2], bl[hh * 4 + 3],
                           smaddr(&sB[(1 * BK + brow) * BSTR + bcol]));
                }
#pragma unroll
                for (int mi = 0; mi < 2; mi++)
#pragma unroll
                    for (int ni = 0; ni < 4; ni++) {
                        int rb = (ni >> 1) * 4 + (ni & 1) * 2;
                        mma16816(accg[mi][ni], ah[mi], bh[rb], bh[rb + 1]);
                        mma16816(accg[mi][ni], ah[mi], bl[rb], bl[rb + 1]);
                        mma16816(accg[mi][ni], al[mi], bh[rb], bh[rb + 1]);
                    }
            }
            // W3 pair -> accu
            {
                uint32_t bh[8], bl[8];
#pragma unroll
                for (int hh = 0; hh < 2; hh++) {
                    int bcol = bcolb + hh * 16;
                    ldsm4t(bh[hh * 4 + 0], bh[hh * 4 + 1], bh[hh * 4 + 2], bh[hh * 4 + 3],
                           smaddr(&sB[(2 * BK + brow) * BSTR + bcol]));
                    ldsm4t(bl[hh * 4 + 0], bl[hh * 4 + 1], bl[hh * 4 + 2], bl[hh * 4 + 3],
                           smaddr(&sB[(3 * BK + brow) * BSTR + bcol]));
                }
#pragma unroll
                for (int mi = 0; mi < 2; mi++)
#pragma unroll
                    for (int ni = 0; ni < 4; ni++) {
                        int rb = (ni >> 1) * 4 + (ni & 1) * 2;
                        mma16816(accu[mi][ni], ah[mi], bh[rb], bh[rb + 1]);
                        mma16816(accu[mi][ni], ah[mi], bl[rb], bl[rb + 1]);
                        mma16816(accu[mi][ni], al[mi], bh[rb], bh[rb + 1]);
                    }
            }
        }
    }

    // epilogue: SwiGLU + split to bf16 hi/lo
#pragma unroll
    for (int mi = 0; mi < 2; mi++)
#pragma unroll
        for (int ni = 0; ni < 4; ni++) {
            int r = row0 + wm * 32 + mi * 16 + (lane >> 2);
            int c = n0 + wn * 32 + ni * 8 + (lane & 3) * 2;
#pragma unroll
            for (int pr = 0; pr < 2; pr++) {
                int rr = r + pr * 8;
                float g0 = accg[mi][ni][pr * 2 + 0];
                float g1 = accg[mi][ni][pr * 2 + 1];
                float u0 = accu[mi][ni][pr * 2 + 0];
                float u1 = accu[mi][ni][pr * 2 + 1];
                float h0 = g0 / (1.0f + expf(-g0)) * u0;
                float h1 = g1 / (1.0f + expf(-g1)) * u1;
                __nv_bfloat16 h0h = __float2bfloat16(h0);
                __nv_bfloat16 h1h = __float2bfloat16(h1);
                __nv_bfloat16 h0l = __float2bfloat16(h0 - __bfloat162float(h0h));
                __nv_bfloat16 h1l = __float2bfloat16(h1 - __bfloat162float(h1h));
                *(__nv_bfloat162*)&g_h_hi[(size_t)rr * HID + c] = __nv_bfloat162(h0h, h1h);
                *(__nv_bfloat162*)&g_h_lo[(size_t)rr * HID + c] = __nv_bfloat162(h0l, h1l);
            }
        }
}

// ---------------- stage 2: ro = h @ W2  [3-stage cp.async, 2 CTAs/SM] ----------------
__global__ __launch_bounds__(256, 2) void stage2_kernel() {
    int mb = blockIdx.x;
    if (mb >= g_n_mblocks) return;
    int e = g_mb_expert[mb];
    const __nv_bfloat16* W2h = g_w2_hi + (size_t)e * HID * DMODEL;
    const __nv_bfloat16* W2l = g_w2_lo + (size_t)e * HID * DMODEL;
    int row0 = mb * BM;
    int n0 = blockIdx.y * BN;

    extern __shared__ char dsm[];
    char* base = dsm;

    int tid = threadIdx.x, lane = tid & 31, warp = tid >> 5;
    int wm = warp >> 1, wn = warp & 1;

    float acc[2][4][4];
#pragma unroll
    for (int mi = 0; mi < 2; mi++)
#pragma unroll
        for (int ni = 0; ni < 4; ni++)
#pragma unroll
            for (int q = 0; q < 4; q++) acc[mi][ni][q] = 0.0f;

    int ar = tid >> 2, ac = (tid & 3) * 8;
    int br = tid >> 3, bc = (tid & 7) * 8;

    const int NIT = HID / BK;

    auto issue = [&](int it, int buf) {
        char* st = base + buf * S2_STAGE;
        __nv_bfloat16* sAh = (__nv_bfloat16*)st;
        __nv_bfloat16* sAl = sAh + BM * ASTR;
        __nv_bfloat16* sB  = sAl + BM * ASTR;
        int kk = it * BK;
#pragma unroll
        for (int hh = 0; hh < 2; hh++) {
            int r = hh * 64 + ar;
            size_t ao = (size_t)(row0 + r) * HID + kk + ac;
            cpa16(smaddr(&sAh[r * ASTR + ac]), &g_h_hi[ao], 16);
            cpa16(smaddr(&sAl[r * ASTR + ac]), &g_h_lo[ao], 16);
        }
        size_t bo = (size_t)(kk + br) * DMODEL + n0 + bc;
        cpa16(smaddr(&sB[(0 * BK + br) * BSTR + bc]), &W2h[bo], 16);
        cpa16(smaddr(&sB[(1 * BK + br) * BSTR + bc]), &W2l[bo], 16);
        cpa_commit();
    };

    issue(0, 0);
    issue(1, 1);

    for (int it = 0; it < NIT; it++) {
        int buf = it % 3;
        cpa_wait<1>();
        __syncthreads();

        char* st = base + buf * S2_STAGE;
        __nv_bfloat16* sAh = (__nv_bfloat16*)st;
        __nv_bfloat16* sAl = sAh + BM * ASTR;
        __nv_bfloat16* sB  = sAl + BM * ASTR;

#pragma unroll
        for (int ks = 0; ks < 2; ks++) {
            int k0 = ks * 16;
            uint32_t ah[2][4], al[2][4];
#pragma unroll
            for (int mi = 0; mi < 2; mi++) {
                int arow = wm * 32 + mi * 16 + (lane & 15);
                int acol = k0 + (lane >> 4) * 8;
                ldsm4(ah[mi][0], ah[mi][1], ah[mi][2], ah[mi][3], smaddr(&sAh[arow * ASTR + acol]));
                ldsm4(al[mi][0], al[mi][1], al[mi][2], al[mi][3], smaddr(&sAl[arow * ASTR + acol]));
            }
            uint32_t bf[2][8];
#pragma unroll
            for (int v = 0; v < 2; v++)
#pragma unroll
                for (int hh = 0; hh < 2; hh++) {
                    int brow = k0 + (lane & 15);
                    int bcol = wn * 32 + hh * 16 + (lane >> 4) * 8;
                    ldsm4t(bf[v][hh * 4 + 0], bf[v][hh * 4 + 1], bf[v][hh * 4 + 2], bf[v][hh * 4 + 3],
                           smaddr(&sB[(v * BK + brow) * BSTR + bcol]));
                }
#pragma unroll
            for (int mi = 0; mi < 2; mi++)
#pragma unroll
                for (int ni = 0; ni < 4; ni++) {
                    int rb = (ni >> 1) * 4 + (ni & 1) * 2;
                    mma16816(acc[mi][ni], ah[mi], bf[0][rb], bf[0][rb + 1]);
                    mma16816(acc[mi][ni], ah[mi], bf[1][rb], bf[1][rb + 1]);
                    mma16816(acc[mi][ni], al[mi], bf[0][rb], bf[0][rb + 1]);
                }
        }

        if (it + 2 < NIT) issue(it + 2, (it + 2) % 3);
        else cpa_commit();
    }

#pragma unroll
    for (int mi = 0; mi < 2; mi++)
#pragma unroll
        for (int ni = 0; ni < 4; ni++) {
            int r = row0 + wm * 32 + mi * 16 + (lane >> 2);
            int c = n0 + wn * 32 + ni * 8 + (lane & 3) * 2;
#pragma unroll
            for (int pr = 0; pr < 2; pr++) {
                int rr = r + pr * 8;
                float2 o = make_float2(acc[mi][ni][pr * 2 + 0], acc[mi][ni][pr * 2 + 1]);
                *(float2*)&g_ro[(size_t)rr * DMODEL + c] = o;
            }
        }
}

// ---------------- combine + losses ----------------
__global__ __launch_bounds__(256) void combine_kernel(float* __restrict__ out) {
    int tok = blockIdx.x;
    int p0 = g_row_pos[tok * 2 + 0];
    int p1 = g_row_pos[tok * 2 + 1];
    int ps = g_seg_start[NEXP] + tok;
    float w0 = g_row_w[p0];
    float w1 = g_row_w[p1];
    const float ws = 1.0f / (float)(TOPK + 1);
    for (int d = threadIdx.x; d < DMODEL; d += 256) {
        float v = w0 * g_ro[(size_t)p0 * DMODEL + d]
                + w1 * g_ro[(size_t)p1 * DMODEL + d]
                + ws * g_ro[(size_t)ps * DMODEL + d];
        out[(size_t)tok * DMODEL + d] = v;
    }
    if (tok == 0 && threadIdx.x == 0) {
        float lb = 0.0f;
        for (int e = 0; e < NEXP; e++)
            lb += (float)g_counts[e] * g_probs_sum[e];
        lb *= (float)NEXP * 0.01f / (16.0f * (float)N_TOK * (float)TOPK);
        out[(size_t)N_TOK * DMODEL + 0] = lb;
        out[(size_t)N_TOK * DMODEL + 1] = 0.001f * g_zsum / (float)N_TOK;
    }
}

// ---------------- launch ----------------
extern "C" void kernel_launch(void* const* d_in, const int* in_sizes, int n_in,
                              void* d_out, int out_size) {
    const float* x   = (const float*)d_in[0];
    const float* wr  = (const float*)d_in[1];
    const float* w1  = (const float*)d_in[2];
    const float* w3  = (const float*)d_in[3];
    const float* w2  = (const float*)d_in[4];
    const float* sw1 = (const float*)d_in[5];
    const float* sw3 = (const float*)d_in[6];
    const float* sw2 = (const float*)d_in[7];
    float* out = (float*)d_out;

    static int s_attr_done = 0;
    if (!s_attr_done) {
        cudaFuncSetAttribute(stage1_kernel, cudaFuncAttributeMaxDynamicSharedMemorySize, S1_TOTAL);
        cudaFuncSetAttribute(stage2_kernel, cudaFuncAttributeMaxDynamicSharedMemorySize, S2_TOTAL);
        s_attr_done = 1;
    }

    const size_t WTOT = 27ull * 1024 * 1024;    // 3*(8M+1M) weight elems
    const int NX = N_TOK * DMODEL;              // 4M

    prep_kernel<<<(NX / 8 + 255) / 256, 256>>>(x);
    splitw_kernel<<<(int)((WTOT / 8 + 255) / 256), 256>>>(w1, w3, w2, sw1, sw3, sw2);
    router_kernel<<<N_TOK, 128>>>(x, wr);
    reduce_kernel<<<NEXP + 1, 256>>>();
    planscatter_kernel<<<1, 1024>>>();
    stage1_kernel<<<dim3(MAX_MBLOCKS, HID / BN), 256, S1_TOTAL>>>();
    stage2_kernel<<<dim3(MAX_MBLOCKS, DMODEL / BN), 256, S2_TOTAL>>>();
    combine_kernel<<<N_TOK, 256>>>(out);
}